// round 13
// baseline (speedup 1.0000x reference)
#include <cuda_runtime.h>
#include <stdint.h>

// ---------------------------------------------------------------------------
// GINE 2-layer GNN, N=25000, E=400000, 64 -> 256 -> 256 -> 128 -> 128 -> 1
// R13: aggregation index-fetch software pipeline — next iteration's eperm
// load issues before current iteration's FMAs, removing one serialized L2
// round trip per loop iteration. Rest identical to R12 (best known).
// ---------------------------------------------------------------------------
#define MAXN 25000
#define MAXE 400000

__device__ float g_bufA[MAXN * 256];
__device__ float g_bufB[MAXN * 256];
__device__ float g_agg1[MAXN * 64];
__device__ float g_agg2[MAXN * 256];
__device__ float g_colsum[4][256];
__device__ float g_colsq[4][256];
__device__ int   g_deg[MAXN];        // zero-init; re-zeroed by scatter each call
__device__ int   g_rowptr[MAXN + 1];
__device__ int   g_fill[MAXN];
__device__ int   g_blocksum[32];
__device__ int   g_scanflag[32];     // zero-init; re-zeroed by scatter each call
__device__ int2  g_eperm[MAXE];
// k-major bf16x2 weight tiles, [nb][kc] order, each tile 128 rows x 16 u32.
__device__ uint32_t g_Bhi[65536];
__device__ uint32_t g_Blo[65536];

__device__ __forceinline__ uint32_t packbf(float fhi, float flo) {
    uint32_t r;
    asm("cvt.rn.bf16x2.f32 %0, %1, %2;" : "=r"(r) : "f"(fhi), "f"(flo));
    return r;
}
__device__ __forceinline__ void cp16(uint32_t saddr, const void* g) {
    asm volatile("cp.async.cg.shared.global [%0], [%1], 16;" :: "r"(saddr), "l"(g));
}
__device__ __forceinline__ void cp_commit() {
    asm volatile("cp.async.commit_group;" ::: "memory");
}
__device__ __forceinline__ void cp_wait0() {
    asm volatile("cp.async.wait_group 0;" ::: "memory");
}
__device__ __forceinline__ void ldsm4(uint32_t& r0, uint32_t& r1,
                                      uint32_t& r2, uint32_t& r3, uint32_t a) {
    asm volatile("ldmatrix.sync.aligned.m8n8.x4.shared.b16 {%0,%1,%2,%3}, [%4];"
                 : "=r"(r0), "=r"(r1), "=r"(r2), "=r"(r3) : "r"(a));
}

// per-block edge_index dtype detect: sample first 256 odd 32-bit words.
__device__ __forceinline__ int detect_idx64(const int* e32) {
    int nz = (threadIdx.x < 256) ? (e32[2 * threadIdx.x + 1] != 0) : 0;
    return __syncthreads_or(nz) ? 0 : 1;
}

// ---------------------------------------------------------------------------
// hist (launch 0): zero BN stats, inline dtype detect, degree histogram.
// ---------------------------------------------------------------------------
__global__ void hist_kernel(const void* __restrict__ eiv, int E) {
    int f = detect_idx64((const int*)eiv);
    int gb = blockIdx.x * blockDim.x + threadIdx.x;
    if (gb < 1024) {
        ((float*)g_colsum)[gb] = 0.f;
        ((float*)g_colsq)[gb]  = 0.f;
    }
    int base = gb * 4;
    if (base >= E) return;
    int cnt = min(4, E - base);
    int d[4];
    bool al = ((E & 3) == 0);
    if (f) {
        const long long* p = (const long long*)eiv;
        if (cnt == 4 && al) {
            longlong2 d01 = *(const longlong2*)(p + E + base);
            longlong2 d23 = *(const longlong2*)(p + E + base + 2);
            d[0] = (int)d01.x; d[1] = (int)d01.y; d[2] = (int)d23.x; d[3] = (int)d23.y;
        } else {
            for (int j = 0; j < cnt; j++) d[j] = (int)p[E + base + j];
        }
    } else {
        const int* p = (const int*)eiv;
        if (cnt == 4 && al) {
            int4 dv = *(const int4*)(p + E + base);
            d[0] = dv.x; d[1] = dv.y; d[2] = dv.z; d[3] = dv.w;
        } else {
            for (int j = 0; j < cnt; j++) d[j] = p[E + base + j];
        }
    }
    for (int j = 0; j < cnt; j++) atomicAdd(&g_deg[d[j]], 1);
}

// ---------------------------------------------------------------------------
// scan (launch 1): fused reduce+scan, decoupled lookback (25 co-resident blocks)
// ---------------------------------------------------------------------------
__global__ void scan_fused_kernel(int N) {
    __shared__ int woff[32];
    __shared__ int boff;
    int tid = threadIdx.x, lane = tid & 31, wid = tid >> 5;
    int b = blockIdx.x;
    int i = b * 1024 + tid;
    int v = (i < N) ? g_deg[i] : 0;
    int incl = v;
#pragma unroll
    for (int o = 1; o < 32; o <<= 1) {
        int t = __shfl_up_sync(0xffffffffu, incl, o);
        if (lane >= o) incl += t;
    }
    if (lane == 31) woff[wid] = incl;
    __syncthreads();
    if (wid == 0) {
        int s = woff[lane];
        int si = s;
#pragma unroll
        for (int o = 1; o < 32; o <<= 1) {
            int t = __shfl_up_sync(0xffffffffu, si, o);
            if (lane >= o) si += t;
        }
        woff[lane] = si - s;
        int total = __shfl_sync(0xffffffffu, si, 31);
        if (lane == 0) {
            atomicExch(&g_blocksum[b], total);
            __threadfence();
            atomicExch(&g_scanflag[b], 1);
        }
        int bs = 0;
        if (lane < b) {
            while (atomicAdd(&g_scanflag[lane], 0) == 0) {}
            bs = atomicAdd(&g_blocksum[lane], 0);
        }
#pragma unroll
        for (int o = 16; o > 0; o >>= 1) bs += __shfl_xor_sync(0xffffffffu, bs, o);
        if (lane == 0) boff = bs;
    }
    __syncthreads();
    int start = boff + woff[wid] + incl - v;
    if (i < N) {
        g_rowptr[i] = start;
        g_fill[i]   = start;
    }
    if (i == N - 1) g_rowptr[N] = start + v;
}

// ---------------------------------------------------------------------------
// scatter (launch 2): CSR scatter + rezero deg/scanflag for next call.
// ---------------------------------------------------------------------------
__global__ void scatter_kernel(const void* __restrict__ eiv, int E, int N) {
    int f = detect_idx64((const int*)eiv);
    int gb = blockIdx.x * blockDim.x + threadIdx.x;
    int base = gb * 4;
    if (base < E) {
        int cnt = min(4, E - base);
        int s[4], d[4];
        bool al = ((E & 3) == 0);
        if (f) {
            const long long* p = (const long long*)eiv;
            if (cnt == 4 && al) {
                longlong2 s01 = *(const longlong2*)(p + base);
                longlong2 s23 = *(const longlong2*)(p + base + 2);
                longlong2 d01 = *(const longlong2*)(p + E + base);
                longlong2 d23 = *(const longlong2*)(p + E + base + 2);
                s[0] = (int)s01.x; s[1] = (int)s01.y; s[2] = (int)s23.x; s[3] = (int)s23.y;
                d[0] = (int)d01.x; d[1] = (int)d01.y; d[2] = (int)d23.x; d[3] = (int)d23.y;
            } else {
                for (int j = 0; j < cnt; j++) { s[j] = (int)p[base + j]; d[j] = (int)p[E + base + j]; }
            }
        } else {
            const int* p = (const int*)eiv;
            if (cnt == 4 && al) {
                int4 sv = *(const int4*)(p + base);
                int4 dv = *(const int4*)(p + E + base);
                s[0] = sv.x; s[1] = sv.y; s[2] = sv.z; s[3] = sv.w;
                d[0] = dv.x; d[1] = dv.y; d[2] = dv.z; d[3] = dv.w;
            } else {
                for (int j = 0; j < cnt; j++) { s[j] = p[base + j]; d[j] = p[E + base + j]; }
            }
        }
        for (int j = 0; j < cnt; j++) {
            int pos = atomicAdd(&g_fill[d[j]], 1);
            g_eperm[pos] = make_int2(s[j], base + j);
        }
    }
    if (gb < N) g_deg[gb] = 0;
    if (gb < 32) g_scanflag[gb] = 0;
}

// ---------------------------------------------------------------------------
// agg1 (launch 3 -> PROFILED): warp per node, d=64, 2 cols/lane, W in regs.
// Software-pipelined index fetch: eperm for iter i+1 issues before iter i's
// compute, hiding one L2 round trip per iteration.
// ---------------------------------------------------------------------------
__global__ void __launch_bounds__(256) agg1_kernel(
    const float* __restrict__ ea,
    const float* __restrict__ We, const float* __restrict__ be,
    const float* __restrict__ x, float* __restrict__ agg, int N)
{
    int tid = threadIdx.x, lane = tid & 31, wid = tid >> 5;
    int node = blockIdx.x * 8 + wid;
    if (node >= N) return;
    int c0 = lane * 2;
    float w0[8], w1[8];
#pragma unroll
    for (int k = 0; k < 8; k++) {
        float2 wv = *(const float2*)(We + k * 64 + c0);
        w0[k] = wv.x; w1[k] = wv.y;
    }
    float2 bv = *(const float2*)(be + c0);
    int beg = g_rowptr[node], end = g_rowptr[node + 1];
    float acc0 = 0.f, acc1 = 0.f;

    int2 pe = make_int2(0, 0);
    if (lane < 2 && beg + lane < end) pe = g_eperm[beg + lane];

    for (int i = beg; i < end; i += 2) {
        int s0 = __shfl_sync(0xffffffffu, pe.x, 0);
        int e0 = __shfl_sync(0xffffffffu, pe.y, 0);
        int s1 = __shfl_sync(0xffffffffu, pe.x, 1);
        int e1 = __shfl_sync(0xffffffffu, pe.y, 1);
        bool has1 = (i + 1 < end);
        int e1s = has1 ? e1 : e0, s1s = has1 ? s1 : s0;

        // issue all gathers for this iteration
        float4 a0 = __ldg((const float4*)(ea + (size_t)e0 * 8));
        float4 a1 = __ldg((const float4*)(ea + (size_t)e0 * 8) + 1);
        float4 b0 = __ldg((const float4*)(ea + (size_t)e1s * 8));
        float4 b1 = __ldg((const float4*)(ea + (size_t)e1s * 8) + 1);
        float2 xa = *(const float2*)(x + (size_t)s0 * 64 + c0);
        float2 xb = *(const float2*)(x + (size_t)s1s * 64 + c0);

        // prefetch next iteration's indices while gathers are in flight
        int2 pen = make_int2(0, 0);
        if (lane < 2 && i + 2 + lane < end) pen = g_eperm[i + 2 + lane];

        float aa[8] = {a0.x, a0.y, a0.z, a0.w, a1.x, a1.y, a1.z, a1.w};
        float ab[8] = {b0.x, b0.y, b0.z, b0.w, b1.x, b1.y, b1.z, b1.w};
        float ma0 = bv.x, ma1 = bv.y, mb0 = bv.x, mb1 = bv.y;
#pragma unroll
        for (int k = 0; k < 8; k++) {
            ma0 += aa[k] * w0[k]; ma1 += aa[k] * w1[k];
            mb0 += ab[k] * w0[k]; mb1 += ab[k] * w1[k];
        }
        acc0 += fmaxf(xa.x + ma0, 0.f);
        acc1 += fmaxf(xa.y + ma1, 0.f);
        if (has1) {
            acc0 += fmaxf(xb.x + mb0, 0.f);
            acc1 += fmaxf(xb.y + mb1, 0.f);
        }
        pe = pen;
    }
    *(float2*)(agg + (size_t)node * 64 + c0) = make_float2(acc0, acc1);
}

// ---------------------------------------------------------------------------
// agg2: 64 threads per node, d=256, 4 cols/lane, W in regs, pipelined indices.
// ---------------------------------------------------------------------------
__global__ void __launch_bounds__(256) agg2_kernel(
    const float* __restrict__ ea,
    const float* __restrict__ We, const float* __restrict__ be,
    const float* __restrict__ h1, float* __restrict__ agg, int N)
{
    int tid = threadIdx.x, lane = tid & 31;
    int node = blockIdx.x * 4 + (tid >> 6);
    if (node >= N) return;
    int c0 = (tid & 63) * 4;
    float w0[8], w1[8], w2[8], w3[8];
#pragma unroll
    for (int k = 0; k < 8; k++) {
        float4 wv = *(const float4*)(We + k * 256 + c0);
        w0[k] = wv.x; w1[k] = wv.y; w2[k] = wv.z; w3[k] = wv.w;
    }
    float4 bv = *(const float4*)(be + c0);
    int beg = g_rowptr[node], end = g_rowptr[node + 1];
    float ac0 = 0.f, ac1 = 0.f, ac2 = 0.f, ac3 = 0.f;

    int2 pe = make_int2(0, 0);
    if (lane < 2 && beg + lane < end) pe = g_eperm[beg + lane];

    for (int i = beg; i < end; i += 2) {
        int s0 = __shfl_sync(0xffffffffu, pe.x, 0);
        int e0 = __shfl_sync(0xffffffffu, pe.y, 0);
        int s1 = __shfl_sync(0xffffffffu, pe.x, 1);
        int e1 = __shfl_sync(0xffffffffu, pe.y, 1);
        bool has1 = (i + 1 < end);
        int e1s = has1 ? e1 : e0, s1s = has1 ? s1 : s0;

        float4 a0 = __ldg((const float4*)(ea + (size_t)e0 * 8));
        float4 a1 = __ldg((const float4*)(ea + (size_t)e0 * 8) + 1);
        float4 b0 = __ldg((const float4*)(ea + (size_t)e1s * 8));
        float4 b1 = __ldg((const float4*)(ea + (size_t)e1s * 8) + 1);
        float4 ha = *(const float4*)(h1 + (size_t)s0 * 256 + c0);
        float4 hb = *(const float4*)(h1 + (size_t)s1s * 256 + c0);

        int2 pen = make_int2(0, 0);
        if (lane < 2 && i + 2 + lane < end) pen = g_eperm[i + 2 + lane];

        float aa[8] = {a0.x, a0.y, a0.z, a0.w, a1.x, a1.y, a1.z, a1.w};
        float ab[8] = {b0.x, b0.y, b0.z, b0.w, b1.x, b1.y, b1.z, b1.w};
        float ma0 = bv.x, ma1 = bv.y, ma2 = bv.z, ma3 = bv.w;
        float mb0 = bv.x, mb1 = bv.y, mb2 = bv.z, mb3 = bv.w;
#pragma unroll
        for (int k = 0; k < 8; k++) {
            ma0 += aa[k] * w0[k]; ma1 += aa[k] * w1[k];
            ma2 += aa[k] * w2[k]; ma3 += aa[k] * w3[k];
            mb0 += ab[k] * w0[k]; mb1 += ab[k] * w1[k];
            mb2 += ab[k] * w2[k]; mb3 += ab[k] * w3[k];
        }
        ac0 += fmaxf(ha.x + ma0, 0.f);
        ac1 += fmaxf(ha.y + ma1, 0.f);
        ac2 += fmaxf(ha.z + ma2, 0.f);
        ac3 += fmaxf(ha.w + ma3, 0.f);
        if (has1) {
            ac0 += fmaxf(hb.x + mb0, 0.f);
            ac1 += fmaxf(hb.y + mb1, 0.f);
            ac2 += fmaxf(hb.z + mb2, 0.f);
            ac3 += fmaxf(hb.w + mb3, 0.f);
        }
        pe = pen;
    }
    *(float4*)(agg + (size_t)node * 256 + c0) = make_float4(ac0, ac1, ac2, ac3);
}

// ---------------------------------------------------------------------------
// wsplit: W[K][N] fp32 -> bf16 hi/lo bf16x2 (packed along K), k-major tiles.
// ---------------------------------------------------------------------------
__global__ void wsplit_kernel(const float* __restrict__ W11,
                              const float* __restrict__ W12,
                              const float* __restrict__ W21,
                              const float* __restrict__ W22) {
    int i = blockIdx.x * blockDim.x + threadIdx.x;   // < 65536
    const float* W; int Ncols, il, ktiles;
    if (i < 8192)        { W = W11; Ncols = 256; il = i;         ktiles = 2; }
    else if (i < 40960)  { W = W12; Ncols = 256; il = i - 8192;  ktiles = 8; }
    else if (i < 57344)  { W = W21; Ncols = 128; il = i - 40960; ktiles = 8; }
    else                 { W = W22; Ncols = 128; il = i - 57344; ktiles = 4; }
    int tile = il >> 11, t = il & 2047;
    int nb = tile / ktiles, kc = tile % ktiles;
    int nloc = t >> 4, j = t & 15;
    int n = nb * 128 + nloc;
    int k = kc * 32 + j * 2;
    float f0 = W[(size_t)k * Ncols + n];
    float f1 = W[(size_t)(k + 1) * Ncols + n];
    uint32_t hi = packbf(f1, f0);
    float l0 = f0 - __uint_as_float(hi << 16);
    float l1 = f1 - __uint_as_float(hi & 0xffff0000u);
    g_Bhi[i] = hi;
    g_Blo[i] = packbf(l1, l0);
}

// ---------------------------------------------------------------------------
// 3xBF16 GEMM (m16n8k16) with ldmatrix fragment loads. (unchanged)
// ---------------------------------------------------------------------------
#define MMA_BF16(d, a, b)                                                     \
    asm volatile(                                                             \
        "mma.sync.aligned.m16n8k16.row.col.f32.bf16.bf16.f32 "                \
        "{%0,%1,%2,%3},{%4,%5,%6,%7},{%8,%9},{%0,%1,%2,%3};"                  \
        : "+f"(d[0]), "+f"(d[1]), "+f"(d[2]), "+f"(d[3])                      \
        : "r"(a[0]), "r"(a[1]), "r"(a[2]), "r"(a[3]), "r"(b[0]), "r"(b[1]))

#define GA(s)   ((s) * 2560)
#define GB(s)   (5120 + (s) * 5120)
#define GSUM    15360
#define GSQ     15488
#define GAF     15616
#define GBF     15872
#define GEMM_SMEM_BYTES (16128 * 4)

template <int K, int NCOLS, int PRE, int LIN, int LOUT>
__global__ void __launch_bounds__(256) gemm_mma(
    const float* __restrict__ X,
    const uint32_t* __restrict__ WBhi, const uint32_t* __restrict__ WBlo,
    const float* __restrict__ bias, float* __restrict__ out,
    const float* __restrict__ X2, const float* __restrict__ eps_ptr,
    const float* __restrict__ gin, const float* __restrict__ btin,
    int N, float invN)
{
    constexpr int BM = 64, BN = 128, BK = 32;
    constexpr int KT = K / BK;
    constexpr int KTILES = K / 32;
    extern __shared__ uint32_t dsm[];
    float* ssum = (float*)(dsm + GSUM);
    float* ssq  = (float*)(dsm + GSQ);
    float* sAf  = (float*)(dsm + GAF);
    float* sBf  = (float*)(dsm + GBF);
    uint32_t sbase = (uint32_t)__cvta_generic_to_shared(dsm);

    int tid = threadIdx.x, lane = tid & 31, wid = tid >> 5;
    int wm = wid & 1, wn = wid >> 1;
    int n0  = blockIdx.x * BM;
    int nb0 = blockIdx.y * BN;

    for (int i = tid; i < BN; i += 256) { ssum[i] = 0.f; ssq[i] = 0.f; }
    if constexpr (PRE == 2) {
        for (int j = tid; j < K; j += 256) {
            float mu = g_colsum[LIN][j] * invN;
            float var = fmaxf(g_colsq[LIN][j] * invN - mu * mu, 0.f);
            float A = gin[j] * rsqrtf(var + 1e-5f);
            sAf[j] = A;
            sBf[j] = btin[j] - A * mu;
        }
    }
    __syncthreads();

    float eps = 0.f;
    if constexpr (PRE == 1) eps = 1.0f + *eps_ptr;

    float acc[2][4][4];
#pragma unroll
    for (int mt = 0; mt < 2; mt++)
#pragma unroll
        for (int nt = 0; nt < 4; nt++)
#pragma unroll
            for (int r = 0; r < 4; r++) acc[mt][nt][r] = 0.f;

    int a_row = tid >> 2;
    int a_q   = tid & 3;
    auto loadA = [&](int kt, float4* av) {
        int row = n0 + a_row;
        av[0] = make_float4(0.f, 0.f, 0.f, 0.f);
        av[1] = make_float4(0.f, 0.f, 0.f, 0.f);
        if (row < N) {
            int gk = kt * BK + a_q * 8;
#pragma unroll
            for (int q = 0; q < 2; q++) {
                int gkq = gk + q * 4;
                float4 v = *(const float4*)(X + (size_t)row * K + gkq);
                if constexpr (PRE == 1) {
                    float4 xv = *(const float4*)(X2 + (size_t)row * K + gkq);
                    v.x = eps * v.x + xv.x; v.y = eps * v.y + xv.y;
                    v.z = eps * v.z + xv.z; v.w = eps * v.w + xv.w;
                } else if constexpr (PRE == 2) {
                    v.x = fmaxf(sAf[gkq]     * v.x + sBf[gkq],     0.f);
                    v.y = fmaxf(sAf[gkq + 1] * v.y + sBf[gkq + 1], 0.f);
                    v.z = fmaxf(sAf[gkq + 2] * v.z + sBf[gkq + 2], 0.f);
                    v.w = fmaxf(sAf[gkq + 3] * v.w + sBf[gkq + 3], 0.f);
                }
                av[q] = v;
            }
        }
    };
    auto storeA = [&](int s, const float4* av) {
        uint32_t h[4], l[4];
#pragma unroll
        for (int q = 0; q < 2; q++) {
            uint32_t h0 = packbf(av[q].y, av[q].x);
            uint32_t h1 = packbf(av[q].w, av[q].z);
            h[q * 2]     = h0;
            h[q * 2 + 1] = h1;
            l[q * 2]     = packbf(av[q].y - __uint_as_float(h0 & 0xffff0000u),
                                  av[q].x - __uint_as_float(h0 << 16));
            l[q * 2 + 1] = packbf(av[q].w - __uint_as_float(h1 & 0xffff0000u),
                                  av[q].z - __uint_as_float(h1 << 16));
        }
        int idx = GA(s) + a_row * 20 + a_q * 4;
        *(uint4*)&dsm[idx]        = make_uint4(h[0], h[1], h[2], h[3]);
        *(uint4*)&dsm[idx + 1280] = make_uint4(l[0], l[1], l[2], l[3]);
    };
    auto loadB = [&](int kt, int s) {
        int tile = blockIdx.y * KTILES + kt;
        const uint32_t* srcH = WBhi + ((size_t)tile << 11);
        const uint32_t* srcL = WBlo + ((size_t)tile << 11);
        uint32_t dH = sbase + GB(s) * 4;
        uint32_t dL = dH + 2560 * 4;
#pragma unroll
        for (int r = 0; r < 2; r++) {
            int c = tid + r * 256;
            uint32_t off = (uint32_t)((c >> 2) * 20 + (c & 3) * 4) * 4;
            cp16(dH + off, srcH + c * 4);
            cp16(dL + off, srcL + c * 4);
        }
        cp_commit();
    };

    {
        float4 av[2];
        loadB(0, 0);
        loadA(0, av);
        storeA(0, av);
        cp_wait0();
        __syncthreads();
    }

    uint32_t aoff = (uint32_t)((wm * 32 + (lane & 7) + ((lane & 8) ? 8 : 0)) * 20
                               + ((lane & 16) ? 4 : 0));
    uint32_t boff = (uint32_t)((wn * 32 + (lane & 7) + ((lane & 16) ? 8 : 0)) * 20
                               + ((lane & 8) ? 4 : 0));

    for (int kt = 0; kt < KT; kt++) {
        int s = kt & 1;
        float4 nav[2];
        if (kt + 1 < KT) { loadB(kt + 1, s ^ 1); loadA(kt + 1, nav); }

#pragma unroll
        for (int ks = 0; ks < 2; ks++) {
            uint32_t ka = ks * 8;
            uint32_t aB = sbase + (GA(s) + ka) * 4;
            uint32_t bB = sbase + (GB(s) + ka) * 4;
            uint32_t ahi[2][4], alo[2][4];
#pragma unroll
            for (int mt = 0; mt < 2; mt++) {
                uint32_t ad = aB + (aoff + mt * 320) * 4;
                ldsm4(ahi[mt][0], ahi[mt][1], ahi[mt][2], ahi[mt][3], ad);
                ldsm4(alo[mt][0], alo[mt][1], alo[mt][2], alo[mt][3], ad + 1280 * 4);
            }
            uint32_t bhi[4][2], blo[4][2];
#pragma unroll
            for (int p = 0; p < 2; p++) {
                uint32_t bd = bB + (boff + p * 320) * 4;
                uint32_t r0, r1, r2, r3;
                ldsm4(r0, r1, r2, r3, bd);
                bhi[p * 2][0] = r0;     bhi[p * 2][1] = r1;
                bhi[p * 2 + 1][0] = r2; bhi[p * 2 + 1][1] = r3;
                ldsm4(r0, r1, r2, r3, bd + 2560 * 4);
                blo[p * 2][0] = r0;     blo[p * 2][1] = r1;
                blo[p * 2 + 1][0] = r2; blo[p * 2 + 1][1] = r3;
            }
#pragma unroll
            for (int mt = 0; mt < 2; mt++)
#pragma unroll
                for (int nt = 0; nt < 4; nt++) {
                    MMA_BF16(acc[mt][nt], ahi[mt], bhi[nt]);
                    MMA_BF16(acc[mt][nt], alo[mt], bhi[nt]);
                    MMA_BF16(acc[mt][nt], ahi[mt], blo[nt]);
                }
        }
        if (kt + 1 < KT) {
            cp_wait0();
            __syncthreads();
            storeA(s ^ 1, nav);
            __syncthreads();
        }
    }

#pragma unroll
    for (int nt = 0; nt < 4; nt++) {
        int cb = wn * 32 + nt * 8 + 2 * (lane & 3);
        float b0 = bias[nb0 + cb], b1 = bias[nb0 + cb + 1];
        float s0 = 0.f, s1 = 0.f, q0 = 0.f, q1 = 0.f;
#pragma unroll
        for (int mt = 0; mt < 2; mt++) {
            int row0 = n0 + wm * 32 + mt * 16 + (lane >> 2);
            float v0 = acc[mt][nt][0] + b0, v1 = acc[mt][nt][1] + b1;
            float v2 = acc[mt][nt][2] + b0, v3 = acc[mt][nt][3] + b1;
            if (row0 < N) {
                *(float2*)(out + (size_t)row0 * NCOLS + nb0 + cb) = make_float2(v0, v1);
                s0 += v0; s1 += v1; q0 += v0 * v0; q1 += v1 * v1;
            }
            if (row0 + 8 < N) {
                *(float2*)(out + (size_t)(row0 + 8) * NCOLS + nb0 + cb) = make_float2(v2, v3);
                s0 += v2; s1 += v3; q0 += v2 * v2; q1 += v3 * v3;
            }
        }
#pragma unroll
        for (int off = 4; off < 32; off <<= 1) {
            s0 += __shfl_xor_sync(0xffffffffu, s0, off);
            s1 += __shfl_xor_sync(0xffffffffu, s1, off);
            q0 += __shfl_xor_sync(0xffffffffu, q0, off);
            q1 += __shfl_xor_sync(0xffffffffu, q1, off);
        }
        if (lane < 4) {
            atomicAdd(&ssum[cb], s0); atomicAdd(&ssum[cb + 1], s1);
            atomicAdd(&ssq[cb],  q0); atomicAdd(&ssq[cb + 1],  q1);
        }
    }
    __syncthreads();
    for (int i = tid; i < BN; i += 256) {
        atomicAdd(&g_colsum[LOUT][nb0 + i], ssum[i]);
        atomicAdd(&g_colsq[LOUT][nb0 + i],  ssq[i]);
    }
}

// ---------------------------------------------------------------------------
// h = relu(bn(in)) with inline affine from layer-1 stats (256 cols)
// ---------------------------------------------------------------------------
__global__ void bnrelu_kernel(const float4* __restrict__ in,
                              float4* __restrict__ outp, int n4,
                              const float* __restrict__ g,
                              const float* __restrict__ bt, float invN)
{
    __shared__ float sA[256], sB[256];
    int tid = threadIdx.x;
    {
        float mu = g_colsum[1][tid] * invN;
        float var = fmaxf(g_colsq[1][tid] * invN - mu * mu, 0.f);
        float A = g[tid] * rsqrtf(var + 1e-5f);
        sA[tid] = A;
        sB[tid] = bt[tid] - A * mu;
    }
    __syncthreads();
    int i = blockIdx.x * 256 + tid;
    if (i >= n4) return;
    int c0 = (i & 63) * 4;
    float4 v = in[i];
    v.x = fmaxf(sA[c0]     * v.x + sB[c0],     0.f);
    v.y = fmaxf(sA[c0 + 1] * v.y + sB[c0 + 1], 0.f);
    v.z = fmaxf(sA[c0 + 2] * v.z + sB[c0 + 2], 0.f);
    v.w = fmaxf(sA[c0 + 3] * v.w + sB[c0 + 3], 0.f);
    outp[i] = v;
}

// ---------------------------------------------------------------------------
// Output head: out[n] = sum_j relu(bn3(t[n,j])) * Wout[j] + bout
// ---------------------------------------------------------------------------
__global__ void __launch_bounds__(256) out_kernel(
    const float* __restrict__ T, const float* __restrict__ Wout,
    const float* __restrict__ bout, float* __restrict__ out, int N,
    const float* __restrict__ g, const float* __restrict__ bt, float invN)
{
    __shared__ float sA[128], sB[128];
    int tid = threadIdx.x;
    if (tid < 128) {
        float mu = g_colsum[3][tid] * invN;
        float var = fmaxf(g_colsq[3][tid] * invN - mu * mu, 0.f);
        float A = g[tid] * rsqrtf(var + 1e-5f);
        sA[tid] = A;
        sB[tid] = bt[tid] - A * mu;
    }
    __syncthreads();
    int wid = tid >> 5, lane = tid & 31;
    int n = blockIdx.x * 8 + wid;
    if (n >= N) return;
    float4 t = ((const float4*)(T + (size_t)n * 128))[lane];
    float4 w = ((const float4*)Wout)[lane];
    int c = lane * 4;
    float s = fmaxf(sA[c]     * t.x + sB[c],     0.f) * w.x
            + fmaxf(sA[c + 1] * t.y + sB[c + 1], 0.f) * w.y
            + fmaxf(sA[c + 2] * t.z + sB[c + 2], 0.f) * w.z
            + fmaxf(sA[c + 3] * t.w + sB[c + 3], 0.f) * w.w;
#pragma unroll
    for (int o = 16; o > 0; o >>= 1)
        s += __shfl_xor_sync(0xffffffffu, s, o);
    if (lane == 0) out[n] = s + bout[0];
}

// ---------------------------------------------------------------------------
extern "C" void kernel_launch(void* const* d_in, const int* in_sizes, int n_in,
                              void* d_out, int out_size)
{
    const float* x    = (const float*)d_in[0];
    const void*  ei   = d_in[1];
    const float* ea   = (const float*)d_in[2];
    const float* eps1 = (const float*)d_in[3];
    const float* We1  = (const float*)d_in[4];
    const float* be1  = (const float*)d_in[5];
    const float* W11  = (const float*)d_in[6];
    const float* b11  = (const float*)d_in[7];
    const float* g11  = (const float*)d_in[8];
    const float* bt11 = (const float*)d_in[9];
    const float* W12  = (const float*)d_in[10];
    const float* b12  = (const float*)d_in[11];
    const float* g1   = (const float*)d_in[12];
    const float* bt1  = (const float*)d_in[13];
    const float* eps2 = (const float*)d_in[14];
    const float* We2  = (const float*)d_in[15];
    const float* be2  = (const float*)d_in[16];
    const float* W21  = (const float*)d_in[17];
    const float* b21  = (const float*)d_in[18];
    const float* g21  = (const float*)d_in[19];
    const float* bt21 = (const float*)d_in[20];
    const float* W22  = (const float*)d_in[21];
    const float* b22  = (const float*)d_in[22];
    const float* g2   = (const float*)d_in[23];
    const float* bt2  = (const float*)d_in[24];
    const float* Wout = (const float*)d_in[25];
    const float* bout = (const float*)d_in[26];

    int N = in_sizes[0] / 64;   // 25000
    int E = in_sizes[2] / 8;    // 400000
    float invN = 1.0f / (float)N;

    float *agg1, *agg2, *bufA, *bufB;
    uint32_t *bhi, *blo;
    cudaGetSymbolAddress((void**)&agg1, g_agg1);
    cudaGetSymbolAddress((void**)&agg2, g_agg2);
    cudaGetSymbolAddress((void**)&bufA, g_bufA);
    cudaGetSymbolAddress((void**)&bufB, g_bufB);
    cudaGetSymbolAddress((void**)&bhi, g_Bhi);
    cudaGetSymbolAddress((void**)&blo, g_Blo);

    static int attr_done = 0;
    if (!attr_done) {
        cudaFuncSetAttribute(gemm_mma<64, 256, 1, 0, 0>,
                             cudaFuncAttributeMaxDynamicSharedMemorySize, GEMM_SMEM_BYTES);
        cudaFuncSetAttribute(gemm_mma<256, 256, 2, 0, 1>,
                             cudaFuncAttributeMaxDynamicSharedMemorySize, GEMM_SMEM_BYTES);
        cudaFuncSetAttribute(gemm_mma<256, 128, 1, 0, 2>,
                             cudaFuncAttributeMaxDynamicSharedMemorySize, GEMM_SMEM_BYTES);
        cudaFuncSetAttribute(gemm_mma<128, 128, 2, 2, 3>,
                             cudaFuncAttributeMaxDynamicSharedMemorySize, GEMM_SMEM_BYTES);
        attr_done = 1;
    }

    int NB = (N + 1023) / 1024;
    int EB = (E + 1023) / 1024;
    int gx = (N + 63) / 64;

    // --- CSR build: launches 0,1,2 ---
    hist_kernel<<<EB, 256>>>(ei, E);
    scan_fused_kernel<<<NB, 1024>>>(N);
    scatter_kernel<<<EB, 256>>>(ei, E, N);

    // --- conv1 (agg1 = launch index 3 -> profiled) ---
    agg1_kernel<<<(N + 7) / 8, 256>>>(ea, We1, be1, x, agg1, N);
    wsplit_kernel<<<256, 256>>>(W11, W12, W21, W22);
    gemm_mma<64, 256, 1, 0, 0><<<dim3(gx, 2), 256, GEMM_SMEM_BYTES>>>(
        x, bhi, blo, b11, bufA, agg1, eps1, nullptr, nullptr, N, invN);
    gemm_mma<256, 256, 2, 0, 1><<<dim3(gx, 2), 256, GEMM_SMEM_BYTES>>>(
        bufA, bhi + 8192, blo + 8192, b12, bufB, nullptr, nullptr, g11, bt11, N, invN);
    bnrelu_kernel<<<(N * 64 + 255) / 256, 256>>>(
        (const float4*)bufB, (float4*)bufA, N * 64, g1, bt1, invN);

    // --- conv2 ---
    agg2_kernel<<<(N + 3) / 4, 256>>>(ea, We2, be2, bufA, agg2, N);
    gemm_mma<256, 128, 1, 0, 2><<<dim3(gx, 1), 256, GEMM_SMEM_BYTES>>>(
        bufA, bhi + 40960, blo + 40960, b21, bufB, agg2, eps2, nullptr, nullptr, N, invN);
    gemm_mma<128, 128, 2, 2, 3><<<dim3(gx, 1), 256, GEMM_SMEM_BYTES>>>(
        bufB, bhi + 57344, blo + 57344, b22, bufA, nullptr, nullptr, g21, bt21, N, invN);

    // --- head ---
    out_kernel<<<(N + 7) / 8, 256>>>(bufA, Wout, bout, (float*)d_out, N, g2, bt2, invN);
}

// round 14
// speedup vs baseline: 1.1785x; 1.1785x over previous
#include <cuda_runtime.h>
#include <stdint.h>

// ---------------------------------------------------------------------------
// GINE 2-layer GNN, N=25000, E=400000, 64 -> 256 -> 256 -> 128 -> 128 -> 1
// R14: R12 baseline (best known, 309.3us) with two strict-subtraction agg
// changes: broadcast eperm loads (shfl distribution deleted) and 128-thread
// agg blocks (finer residency granularity under degree imbalance).
// ---------------------------------------------------------------------------
#define MAXN 25000
#define MAXE 400000

__device__ float g_bufA[MAXN * 256];
__device__ float g_bufB[MAXN * 256];
__device__ float g_agg1[MAXN * 64];
__device__ float g_agg2[MAXN * 256];
__device__ float g_colsum[4][256];
__device__ float g_colsq[4][256];
__device__ int   g_deg[MAXN];        // zero-init; re-zeroed by scatter each call
__device__ int   g_rowptr[MAXN + 1];
__device__ int   g_fill[MAXN];
__device__ int   g_blocksum[32];
__device__ int   g_scanflag[32];     // zero-init; re-zeroed by scatter each call
__device__ int2  g_eperm[MAXE];
// k-major bf16x2 weight tiles, [nb][kc] order, each tile 128 rows x 16 u32.
__device__ uint32_t g_Bhi[65536];
__device__ uint32_t g_Blo[65536];

__device__ __forceinline__ uint32_t packbf(float fhi, float flo) {
    uint32_t r;
    asm("cvt.rn.bf16x2.f32 %0, %1, %2;" : "=r"(r) : "f"(fhi), "f"(flo));
    return r;
}
__device__ __forceinline__ void cp16(uint32_t saddr, const void* g) {
    asm volatile("cp.async.cg.shared.global [%0], [%1], 16;" :: "r"(saddr), "l"(g));
}
__device__ __forceinline__ void cp_commit() {
    asm volatile("cp.async.commit_group;" ::: "memory");
}
__device__ __forceinline__ void cp_wait0() {
    asm volatile("cp.async.wait_group 0;" ::: "memory");
}
__device__ __forceinline__ void ldsm4(uint32_t& r0, uint32_t& r1,
                                      uint32_t& r2, uint32_t& r3, uint32_t a) {
    asm volatile("ldmatrix.sync.aligned.m8n8.x4.shared.b16 {%0,%1,%2,%3}, [%4];"
                 : "=r"(r0), "=r"(r1), "=r"(r2), "=r"(r3) : "r"(a));
}

// per-block edge_index dtype detect: sample first 256 odd 32-bit words.
__device__ __forceinline__ int detect_idx64(const int* e32) {
    int nz = (threadIdx.x < 256) ? (e32[2 * threadIdx.x + 1] != 0) : 0;
    return __syncthreads_or(nz) ? 0 : 1;
}

// ---------------------------------------------------------------------------
// hist (launch 0): zero BN stats, inline dtype detect, degree histogram.
// ---------------------------------------------------------------------------
__global__ void hist_kernel(const void* __restrict__ eiv, int E) {
    int f = detect_idx64((const int*)eiv);
    int gb = blockIdx.x * blockDim.x + threadIdx.x;
    if (gb < 1024) {
        ((float*)g_colsum)[gb] = 0.f;
        ((float*)g_colsq)[gb]  = 0.f;
    }
    int base = gb * 4;
    if (base >= E) return;
    int cnt = min(4, E - base);
    int d[4];
    bool al = ((E & 3) == 0);
    if (f) {
        const long long* p = (const long long*)eiv;
        if (cnt == 4 && al) {
            longlong2 d01 = *(const longlong2*)(p + E + base);
            longlong2 d23 = *(const longlong2*)(p + E + base + 2);
            d[0] = (int)d01.x; d[1] = (int)d01.y; d[2] = (int)d23.x; d[3] = (int)d23.y;
        } else {
            for (int j = 0; j < cnt; j++) d[j] = (int)p[E + base + j];
        }
    } else {
        const int* p = (const int*)eiv;
        if (cnt == 4 && al) {
            int4 dv = *(const int4*)(p + E + base);
            d[0] = dv.x; d[1] = dv.y; d[2] = dv.z; d[3] = dv.w;
        } else {
            for (int j = 0; j < cnt; j++) d[j] = p[E + base + j];
        }
    }
    for (int j = 0; j < cnt; j++) atomicAdd(&g_deg[d[j]], 1);
}

// ---------------------------------------------------------------------------
// scan (launch 1): fused reduce+scan, decoupled lookback (25 co-resident blocks)
// ---------------------------------------------------------------------------
__global__ void scan_fused_kernel(int N) {
    __shared__ int woff[32];
    __shared__ int boff;
    int tid = threadIdx.x, lane = tid & 31, wid = tid >> 5;
    int b = blockIdx.x;
    int i = b * 1024 + tid;
    int v = (i < N) ? g_deg[i] : 0;
    int incl = v;
#pragma unroll
    for (int o = 1; o < 32; o <<= 1) {
        int t = __shfl_up_sync(0xffffffffu, incl, o);
        if (lane >= o) incl += t;
    }
    if (lane == 31) woff[wid] = incl;
    __syncthreads();
    if (wid == 0) {
        int s = woff[lane];
        int si = s;
#pragma unroll
        for (int o = 1; o < 32; o <<= 1) {
            int t = __shfl_up_sync(0xffffffffu, si, o);
            if (lane >= o) si += t;
        }
        woff[lane] = si - s;
        int total = __shfl_sync(0xffffffffu, si, 31);
        if (lane == 0) {
            atomicExch(&g_blocksum[b], total);
            __threadfence();
            atomicExch(&g_scanflag[b], 1);
        }
        int bs = 0;
        if (lane < b) {
            while (atomicAdd(&g_scanflag[lane], 0) == 0) {}
            bs = atomicAdd(&g_blocksum[lane], 0);
        }
#pragma unroll
        for (int o = 16; o > 0; o >>= 1) bs += __shfl_xor_sync(0xffffffffu, bs, o);
        if (lane == 0) boff = bs;
    }
    __syncthreads();
    int start = boff + woff[wid] + incl - v;
    if (i < N) {
        g_rowptr[i] = start;
        g_fill[i]   = start;
    }
    if (i == N - 1) g_rowptr[N] = start + v;
}

// ---------------------------------------------------------------------------
// scatter (launch 2): CSR scatter + rezero deg/scanflag for next call.
// ---------------------------------------------------------------------------
__global__ void scatter_kernel(const void* __restrict__ eiv, int E, int N) {
    int f = detect_idx64((const int*)eiv);
    int gb = blockIdx.x * blockDim.x + threadIdx.x;
    int base = gb * 4;
    if (base < E) {
        int cnt = min(4, E - base);
        int s[4], d[4];
        bool al = ((E & 3) == 0);
        if (f) {
            const long long* p = (const long long*)eiv;
            if (cnt == 4 && al) {
                longlong2 s01 = *(const longlong2*)(p + base);
                longlong2 s23 = *(const longlong2*)(p + base + 2);
                longlong2 d01 = *(const longlong2*)(p + E + base);
                longlong2 d23 = *(const longlong2*)(p + E + base + 2);
                s[0] = (int)s01.x; s[1] = (int)s01.y; s[2] = (int)s23.x; s[3] = (int)s23.y;
                d[0] = (int)d01.x; d[1] = (int)d01.y; d[2] = (int)d23.x; d[3] = (int)d23.y;
            } else {
                for (int j = 0; j < cnt; j++) { s[j] = (int)p[base + j]; d[j] = (int)p[E + base + j]; }
            }
        } else {
            const int* p = (const int*)eiv;
            if (cnt == 4 && al) {
                int4 sv = *(const int4*)(p + base);
                int4 dv = *(const int4*)(p + E + base);
                s[0] = sv.x; s[1] = sv.y; s[2] = sv.z; s[3] = sv.w;
                d[0] = dv.x; d[1] = dv.y; d[2] = dv.z; d[3] = dv.w;
            } else {
                for (int j = 0; j < cnt; j++) { s[j] = p[base + j]; d[j] = p[E + base + j]; }
            }
        }
        for (int j = 0; j < cnt; j++) {
            int pos = atomicAdd(&g_fill[d[j]], 1);
            g_eperm[pos] = make_int2(s[j], base + j);
        }
    }
    if (gb < N) g_deg[gb] = 0;
    if (gb < 32) g_scanflag[gb] = 0;
}

// ---------------------------------------------------------------------------
// agg1 (launch 3 -> PROFILED): warp per node, d=64, 2 cols/lane, W in regs.
// Broadcast eperm loads (no shfl), 128-thread blocks.
// ---------------------------------------------------------------------------
__global__ void __launch_bounds__(128) agg1_kernel(
    const float* __restrict__ ea,
    const float* __restrict__ We, const float* __restrict__ be,
    const float* __restrict__ x, float* __restrict__ agg, int N)
{
    int tid = threadIdx.x, lane = tid & 31, wid = tid >> 5;
    int node = blockIdx.x * 4 + wid;
    if (node >= N) return;
    int c0 = lane * 2;
    float w0[8], w1[8];
#pragma unroll
    for (int k = 0; k < 8; k++) {
        float2 wv = *(const float2*)(We + k * 64 + c0);
        w0[k] = wv.x; w1[k] = wv.y;
    }
    float2 bv = *(const float2*)(be + c0);
    int beg = g_rowptr[node], end = g_rowptr[node + 1];
    float acc0 = 0.f, acc1 = 0.f;

    for (int i = beg; i < end; i += 2) {
        int2 p0 = __ldg(&g_eperm[i]);                    // broadcast
        bool has1 = (i + 1 < end);
        int2 p1 = has1 ? __ldg(&g_eperm[i + 1]) : p0;    // broadcast

        float4 a0 = __ldg((const float4*)(ea + (size_t)p0.y * 8));
        float4 a1 = __ldg((const float4*)(ea + (size_t)p0.y * 8) + 1);
        float4 b0 = __ldg((const float4*)(ea + (size_t)p1.y * 8));
        float4 b1 = __ldg((const float4*)(ea + (size_t)p1.y * 8) + 1);
        float2 xa = *(const float2*)(x + (size_t)p0.x * 64 + c0);
        float2 xb = *(const float2*)(x + (size_t)p1.x * 64 + c0);

        float aa[8] = {a0.x, a0.y, a0.z, a0.w, a1.x, a1.y, a1.z, a1.w};
        float ab[8] = {b0.x, b0.y, b0.z, b0.w, b1.x, b1.y, b1.z, b1.w};
        float ma0 = bv.x, ma1 = bv.y, mb0 = bv.x, mb1 = bv.y;
#pragma unroll
        for (int k = 0; k < 8; k++) {
            ma0 += aa[k] * w0[k]; ma1 += aa[k] * w1[k];
            mb0 += ab[k] * w0[k]; mb1 += ab[k] * w1[k];
        }
        acc0 += fmaxf(xa.x + ma0, 0.f);
        acc1 += fmaxf(xa.y + ma1, 0.f);
        if (has1) {
            acc0 += fmaxf(xb.x + mb0, 0.f);
            acc1 += fmaxf(xb.y + mb1, 0.f);
        }
    }
    *(float2*)(agg + (size_t)node * 64 + c0) = make_float2(acc0, acc1);
}

// ---------------------------------------------------------------------------
// agg2: 64 threads per node, d=256, 4 cols/lane, W in regs.
// Broadcast eperm loads (no shfl), 128-thread blocks (2 nodes/block).
// ---------------------------------------------------------------------------
__global__ void __launch_bounds__(128) agg2_kernel(
    const float* __restrict__ ea,
    const float* __restrict__ We, const float* __restrict__ be,
    const float* __restrict__ h1, float* __restrict__ agg, int N)
{
    int tid = threadIdx.x;
    int node = blockIdx.x * 2 + (tid >> 6);
    if (node >= N) return;
    int c0 = (tid & 63) * 4;
    float w0[8], w1[8], w2[8], w3[8];
#pragma unroll
    for (int k = 0; k < 8; k++) {
        float4 wv = *(const float4*)(We + k * 256 + c0);
        w0[k] = wv.x; w1[k] = wv.y; w2[k] = wv.z; w3[k] = wv.w;
    }
    float4 bv = *(const float4*)(be + c0);
    int beg = g_rowptr[node], end = g_rowptr[node + 1];
    float ac0 = 0.f, ac1 = 0.f, ac2 = 0.f, ac3 = 0.f;

    for (int i = beg; i < end; i += 2) {
        int2 p0 = __ldg(&g_eperm[i]);
        bool has1 = (i + 1 < end);
        int2 p1 = has1 ? __ldg(&g_eperm[i + 1]) : p0;

        float4 a0 = __ldg((const float4*)(ea + (size_t)p0.y * 8));
        float4 a1 = __ldg((const float4*)(ea + (size_t)p0.y * 8) + 1);
        float4 b0 = __ldg((const float4*)(ea + (size_t)p1.y * 8));
        float4 b1 = __ldg((const float4*)(ea + (size_t)p1.y * 8) + 1);
        float4 ha = *(const float4*)(h1 + (size_t)p0.x * 256 + c0);
        float4 hb = *(const float4*)(h1 + (size_t)p1.x * 256 + c0);

        float aa[8] = {a0.x, a0.y, a0.z, a0.w, a1.x, a1.y, a1.z, a1.w};
        float ab[8] = {b0.x, b0.y, b0.z, b0.w, b1.x, b1.y, b1.z, b1.w};
        float ma0 = bv.x, ma1 = bv.y, ma2 = bv.z, ma3 = bv.w;
        float mb0 = bv.x, mb1 = bv.y, mb2 = bv.z, mb3 = bv.w;
#pragma unroll
        for (int k = 0; k < 8; k++) {
            ma0 += aa[k] * w0[k]; ma1 += aa[k] * w1[k];
            ma2 += aa[k] * w2[k]; ma3 += aa[k] * w3[k];
            mb0 += ab[k] * w0[k]; mb1 += ab[k] * w1[k];
            mb2 += ab[k] * w2[k]; mb3 += ab[k] * w3[k];
        }
        ac0 += fmaxf(ha.x + ma0, 0.f);
        ac1 += fmaxf(ha.y + ma1, 0.f);
        ac2 += fmaxf(ha.z + ma2, 0.f);
        ac3 += fmaxf(ha.w + ma3, 0.f);
        if (has1) {
            ac0 += fmaxf(hb.x + mb0, 0.f);
            ac1 += fmaxf(hb.y + mb1, 0.f);
            ac2 += fmaxf(hb.z + mb2, 0.f);
            ac3 += fmaxf(hb.w + mb3, 0.f);
        }
    }
    *(float4*)(agg + (size_t)node * 256 + c0) = make_float4(ac0, ac1, ac2, ac3);
}

// ---------------------------------------------------------------------------
// wsplit: W[K][N] fp32 -> bf16 hi/lo bf16x2 (packed along K), k-major tiles.
// ---------------------------------------------------------------------------
__global__ void wsplit_kernel(const float* __restrict__ W11,
                              const float* __restrict__ W12,
                              const float* __restrict__ W21,
                              const float* __restrict__ W22) {
    int i = blockIdx.x * blockDim.x + threadIdx.x;   // < 65536
    const float* W; int Ncols, il, ktiles;
    if (i < 8192)        { W = W11; Ncols = 256; il = i;         ktiles = 2; }
    else if (i < 40960)  { W = W12; Ncols = 256; il = i - 8192;  ktiles = 8; }
    else if (i < 57344)  { W = W21; Ncols = 128; il = i - 40960; ktiles = 8; }
    else                 { W = W22; Ncols = 128; il = i - 57344; ktiles = 4; }
    int tile = il >> 11, t = il & 2047;
    int nb = tile / ktiles, kc = tile % ktiles;
    int nloc = t >> 4, j = t & 15;
    int n = nb * 128 + nloc;
    int k = kc * 32 + j * 2;
    float f0 = W[(size_t)k * Ncols + n];
    float f1 = W[(size_t)(k + 1) * Ncols + n];
    uint32_t hi = packbf(f1, f0);
    float l0 = f0 - __uint_as_float(hi << 16);
    float l1 = f1 - __uint_as_float(hi & 0xffff0000u);
    g_Bhi[i] = hi;
    g_Blo[i] = packbf(l1, l0);
}

// ---------------------------------------------------------------------------
// 3xBF16 GEMM (m16n8k16) with ldmatrix fragment loads. (unchanged)
// ---------------------------------------------------------------------------
#define MMA_BF16(d, a, b)                                                     \
    asm volatile(                                                             \
        "mma.sync.aligned.m16n8k16.row.col.f32.bf16.bf16.f32 "                \
        "{%0,%1,%2,%3},{%4,%5,%6,%7},{%8,%9},{%0,%1,%2,%3};"                  \
        : "+f"(d[0]), "+f"(d[1]), "+f"(d[2]), "+f"(d[3])                      \
        : "r"(a[0]), "r"(a[1]), "r"(a[2]), "r"(a[3]), "r"(b[0]), "r"(b[1]))

#define GA(s)   ((s) * 2560)
#define GB(s)   (5120 + (s) * 5120)
#define GSUM    15360
#define GSQ     15488
#define GAF     15616
#define GBF     15872
#define GEMM_SMEM_BYTES (16128 * 4)

template <int K, int NCOLS, int PRE, int LIN, int LOUT>
__global__ void __launch_bounds__(256) gemm_mma(
    const float* __restrict__ X,
    const uint32_t* __restrict__ WBhi, const uint32_t* __restrict__ WBlo,
    const float* __restrict__ bias, float* __restrict__ out,
    const float* __restrict__ X2, const float* __restrict__ eps_ptr,
    const float* __restrict__ gin, const float* __restrict__ btin,
    int N, float invN)
{
    constexpr int BM = 64, BN = 128, BK = 32;
    constexpr int KT = K / BK;
    constexpr int KTILES = K / 32;
    extern __shared__ uint32_t dsm[];
    float* ssum = (float*)(dsm + GSUM);
    float* ssq  = (float*)(dsm + GSQ);
    float* sAf  = (float*)(dsm + GAF);
    float* sBf  = (float*)(dsm + GBF);
    uint32_t sbase = (uint32_t)__cvta_generic_to_shared(dsm);

    int tid = threadIdx.x, lane = tid & 31, wid = tid >> 5;
    int wm = wid & 1, wn = wid >> 1;
    int n0  = blockIdx.x * BM;
    int nb0 = blockIdx.y * BN;

    for (int i = tid; i < BN; i += 256) { ssum[i] = 0.f; ssq[i] = 0.f; }
    if constexpr (PRE == 2) {
        for (int j = tid; j < K; j += 256) {
            float mu = g_colsum[LIN][j] * invN;
            float var = fmaxf(g_colsq[LIN][j] * invN - mu * mu, 0.f);
            float A = gin[j] * rsqrtf(var + 1e-5f);
            sAf[j] = A;
            sBf[j] = btin[j] - A * mu;
        }
    }
    __syncthreads();

    float eps = 0.f;
    if constexpr (PRE == 1) eps = 1.0f + *eps_ptr;

    float acc[2][4][4];
#pragma unroll
    for (int mt = 0; mt < 2; mt++)
#pragma unroll
        for (int nt = 0; nt < 4; nt++)
#pragma unroll
            for (int r = 0; r < 4; r++) acc[mt][nt][r] = 0.f;

    int a_row = tid >> 2;
    int a_q   = tid & 3;
    auto loadA = [&](int kt, float4* av) {
        int row = n0 + a_row;
        av[0] = make_float4(0.f, 0.f, 0.f, 0.f);
        av[1] = make_float4(0.f, 0.f, 0.f, 0.f);
        if (row < N) {
            int gk = kt * BK + a_q * 8;
#pragma unroll
            for (int q = 0; q < 2; q++) {
                int gkq = gk + q * 4;
                float4 v = *(const float4*)(X + (size_t)row * K + gkq);
                if constexpr (PRE == 1) {
                    float4 xv = *(const float4*)(X2 + (size_t)row * K + gkq);
                    v.x = eps * v.x + xv.x; v.y = eps * v.y + xv.y;
                    v.z = eps * v.z + xv.z; v.w = eps * v.w + xv.w;
                } else if constexpr (PRE == 2) {
                    v.x = fmaxf(sAf[gkq]     * v.x + sBf[gkq],     0.f);
                    v.y = fmaxf(sAf[gkq + 1] * v.y + sBf[gkq + 1], 0.f);
                    v.z = fmaxf(sAf[gkq + 2] * v.z + sBf[gkq + 2], 0.f);
                    v.w = fmaxf(sAf[gkq + 3] * v.w + sBf[gkq + 3], 0.f);
                }
                av[q] = v;
            }
        }
    };
    auto storeA = [&](int s, const float4* av) {
        uint32_t h[4], l[4];
#pragma unroll
        for (int q = 0; q < 2; q++) {
            uint32_t h0 = packbf(av[q].y, av[q].x);
            uint32_t h1 = packbf(av[q].w, av[q].z);
            h[q * 2]     = h0;
            h[q * 2 + 1] = h1;
            l[q * 2]     = packbf(av[q].y - __uint_as_float(h0 & 0xffff0000u),
                                  av[q].x - __uint_as_float(h0 << 16));
            l[q * 2 + 1] = packbf(av[q].w - __uint_as_float(h1 & 0xffff0000u),
                                  av[q].z - __uint_as_float(h1 << 16));
        }
        int idx = GA(s) + a_row * 20 + a_q * 4;
        *(uint4*)&dsm[idx]        = make_uint4(h[0], h[1], h[2], h[3]);
        *(uint4*)&dsm[idx + 1280] = make_uint4(l[0], l[1], l[2], l[3]);
    };
    auto loadB = [&](int kt, int s) {
        int tile = blockIdx.y * KTILES + kt;
        const uint32_t* srcH = WBhi + ((size_t)tile << 11);
        const uint32_t* srcL = WBlo + ((size_t)tile << 11);
        uint32_t dH = sbase + GB(s) * 4;
        uint32_t dL = dH + 2560 * 4;
#pragma unroll
        for (int r = 0; r < 2; r++) {
            int c = tid + r * 256;
            uint32_t off = (uint32_t)((c >> 2) * 20 + (c & 3) * 4) * 4;
            cp16(dH + off, srcH + c * 4);
            cp16(dL + off, srcL + c * 4);
        }
        cp_commit();
    };

    {
        float4 av[2];
        loadB(0, 0);
        loadA(0, av);
        storeA(0, av);
        cp_wait0();
        __syncthreads();
    }

    uint32_t aoff = (uint32_t)((wm * 32 + (lane & 7) + ((lane & 8) ? 8 : 0)) * 20
                               + ((lane & 16) ? 4 : 0));
    uint32_t boff = (uint32_t)((wn * 32 + (lane & 7) + ((lane & 16) ? 8 : 0)) * 20
                               + ((lane & 8) ? 4 : 0));

    for (int kt = 0; kt < KT; kt++) {
        int s = kt & 1;
        float4 nav[2];
        if (kt + 1 < KT) { loadB(kt + 1, s ^ 1); loadA(kt + 1, nav); }

#pragma unroll
        for (int ks = 0; ks < 2; ks++) {
            uint32_t ka = ks * 8;
            uint32_t aB = sbase + (GA(s) + ka) * 4;
            uint32_t bB = sbase + (GB(s) + ka) * 4;
            uint32_t ahi[2][4], alo[2][4];
#pragma unroll
            for (int mt = 0; mt < 2; mt++) {
                uint32_t ad = aB + (aoff + mt * 320) * 4;
                ldsm4(ahi[mt][0], ahi[mt][1], ahi[mt][2], ahi[mt][3], ad);
                ldsm4(alo[mt][0], alo[mt][1], alo[mt][2], alo[mt][3], ad + 1280 * 4);
            }
            uint32_t bhi[4][2], blo[4][2];
#pragma unroll
            for (int p = 0; p < 2; p++) {
                uint32_t bd = bB + (boff + p * 320) * 4;
                uint32_t r0, r1, r2, r3;
                ldsm4(r0, r1, r2, r3, bd);
                bhi[p * 2][0] = r0;     bhi[p * 2][1] = r1;
                bhi[p * 2 + 1][0] = r2; bhi[p * 2 + 1][1] = r3;
                ldsm4(r0, r1, r2, r3, bd + 2560 * 4);
                blo[p * 2][0] = r0;     blo[p * 2][1] = r1;
                blo[p * 2 + 1][0] = r2; blo[p * 2 + 1][1] = r3;
            }
#pragma unroll
            for (int mt = 0; mt < 2; mt++)
#pragma unroll
                for (int nt = 0; nt < 4; nt++) {
                    MMA_BF16(acc[mt][nt], ahi[mt], bhi[nt]);
                    MMA_BF16(acc[mt][nt], alo[mt], bhi[nt]);
                    MMA_BF16(acc[mt][nt], ahi[mt], blo[nt]);
                }
        }
        if (kt + 1 < KT) {
            cp_wait0();
            __syncthreads();
            storeA(s ^ 1, nav);
            __syncthreads();
        }
    }

#pragma unroll
    for (int nt = 0; nt < 4; nt++) {
        int cb = wn * 32 + nt * 8 + 2 * (lane & 3);
        float b0 = bias[nb0 + cb], b1 = bias[nb0 + cb + 1];
        float s0 = 0.f, s1 = 0.f, q0 = 0.f, q1 = 0.f;
#pragma unroll
        for (int mt = 0; mt < 2; mt++) {
            int row0 = n0 + wm * 32 + mt * 16 + (lane >> 2);
            float v0 = acc[mt][nt][0] + b0, v1 = acc[mt][nt][1] + b1;
            float v2 = acc[mt][nt][2] + b0, v3 = acc[mt][nt][3] + b1;
            if (row0 < N) {
                *(float2*)(out + (size_t)row0 * NCOLS + nb0 + cb) = make_float2(v0, v1);
                s0 += v0; s1 += v1; q0 += v0 * v0; q1 += v1 * v1;
            }
            if (row0 + 8 < N) {
                *(float2*)(out + (size_t)(row0 + 8) * NCOLS + nb0 + cb) = make_float2(v2, v3);
                s0 += v2; s1 += v3; q0 += v2 * v2; q1 += v3 * v3;
            }
        }
#pragma unroll
        for (int off = 4; off < 32; off <<= 1) {
            s0 += __shfl_xor_sync(0xffffffffu, s0, off);
            s1 += __shfl_xor_sync(0xffffffffu, s1, off);
            q0 += __shfl_xor_sync(0xffffffffu, q0, off);
            q1 += __shfl_xor_sync(0xffffffffu, q1, off);
        }
        if (lane < 4) {
            atomicAdd(&ssum[cb], s0); atomicAdd(&ssum[cb + 1], s1);
            atomicAdd(&ssq[cb],  q0); atomicAdd(&ssq[cb + 1],  q1);
        }
    }
    __syncthreads();
    for (int i = tid; i < BN; i += 256) {
        atomicAdd(&g_colsum[LOUT][nb0 + i], ssum[i]);
        atomicAdd(&g_colsq[LOUT][nb0 + i],  ssq[i]);
    }
}

// ---------------------------------------------------------------------------
// h = relu(bn(in)) with inline affine from layer-1 stats (256 cols)
// ---------------------------------------------------------------------------
__global__ void bnrelu_kernel(const float4* __restrict__ in,
                              float4* __restrict__ outp, int n4,
                              const float* __restrict__ g,
                              const float* __restrict__ bt, float invN)
{
    __shared__ float sA[256], sB[256];
    int tid = threadIdx.x;
    {
        float mu = g_colsum[1][tid] * invN;
        float var = fmaxf(g_colsq[1][tid] * invN - mu * mu, 0.f);
        float A = g[tid] * rsqrtf(var + 1e-5f);
        sA[tid] = A;
        sB[tid] = bt[tid] - A * mu;
    }
    __syncthreads();
    int i = blockIdx.x * 256 + tid;
    if (i >= n4) return;
    int c0 = (i & 63) * 4;
    float4 v = in[i];
    v.x = fmaxf(sA[c0]     * v.x + sB[c0],     0.f);
    v.y = fmaxf(sA[c0 + 1] * v.y + sB[c0 + 1], 0.f);
    v.z = fmaxf(sA[c0 + 2] * v.z + sB[c0 + 2], 0.f);
    v.w = fmaxf(sA[c0 + 3] * v.w + sB[c0 + 3], 0.f);
    outp[i] = v;
}

// ---------------------------------------------------------------------------
// Output head: out[n] = sum_j relu(bn3(t[n,j])) * Wout[j] + bout
// ---------------------------------------------------------------------------
__global__ void __launch_bounds__(256) out_kernel(
    const float* __restrict__ T, const float* __restrict__ Wout,
    const float* __restrict__ bout, float* __restrict__ out, int N,
    const float* __restrict__ g, const float* __restrict__ bt, float invN)
{
    __shared__ float sA[128], sB[128];
    int tid = threadIdx.x;
    if (tid < 128) {
        float mu = g_colsum[3][tid] * invN;
        float var = fmaxf(g_colsq[3][tid] * invN - mu * mu, 0.f);
        float A = g[tid] * rsqrtf(var + 1e-5f);
        sA[tid] = A;
        sB[tid] = bt[tid] - A * mu;
    }
    __syncthreads();
    int wid = tid >> 5, lane = tid & 31;
    int n = blockIdx.x * 8 + wid;
    if (n >= N) return;
    float4 t = ((const float4*)(T + (size_t)n * 128))[lane];
    float4 w = ((const float4*)Wout)[lane];
    int c = lane * 4;
    float s = fmaxf(sA[c]     * t.x + sB[c],     0.f) * w.x
            + fmaxf(sA[c + 1] * t.y + sB[c + 1], 0.f) * w.y
            + fmaxf(sA[c + 2] * t.z + sB[c + 2], 0.f) * w.z
            + fmaxf(sA[c + 3] * t.w + sB[c + 3], 0.f) * w.w;
#pragma unroll
    for (int o = 16; o > 0; o >>= 1)
        s += __shfl_xor_sync(0xffffffffu, s, o);
    if (lane == 0) out[n] = s + bout[0];
}

// ---------------------------------------------------------------------------
extern "C" void kernel_launch(void* const* d_in, const int* in_sizes, int n_in,
                              void* d_out, int out_size)
{
    const float* x    = (const float*)d_in[0];
    const void*  ei   = d_in[1];
    const float* ea   = (const float*)d_in[2];
    const float* eps1 = (const float*)d_in[3];
    const float* We1  = (const float*)d_in[4];
    const float* be1  = (const float*)d_in[5];
    const float* W11  = (const float*)d_in[6];
    const float* b11  = (const float*)d_in[7];
    const float* g11  = (const float*)d_in[8];
    const float* bt11 = (const float*)d_in[9];
    const float* W12  = (const float*)d_in[10];
    const float* b12  = (const float*)d_in[11];
    const float* g1   = (const float*)d_in[12];
    const float* bt1  = (const float*)d_in[13];
    const float* eps2 = (const float*)d_in[14];
    const float* We2  = (const float*)d_in[15];
    const float* be2  = (const float*)d_in[16];
    const float* W21  = (const float*)d_in[17];
    const float* b21  = (const float*)d_in[18];
    const float* g21  = (const float*)d_in[19];
    const float* bt21 = (const float*)d_in[20];
    const float* W22  = (const float*)d_in[21];
    const float* b22  = (const float*)d_in[22];
    const float* g2   = (const float*)d_in[23];
    const float* bt2  = (const float*)d_in[24];
    const float* Wout = (const float*)d_in[25];
    const float* bout = (const float*)d_in[26];

    int N = in_sizes[0] / 64;   // 25000
    int E = in_sizes[2] / 8;    // 400000
    float invN = 1.0f / (float)N;

    float *agg1, *agg2, *bufA, *bufB;
    uint32_t *bhi, *blo;
    cudaGetSymbolAddress((void**)&agg1, g_agg1);
    cudaGetSymbolAddress((void**)&agg2, g_agg2);
    cudaGetSymbolAddress((void**)&bufA, g_bufA);
    cudaGetSymbolAddress((void**)&bufB, g_bufB);
    cudaGetSymbolAddress((void**)&bhi, g_Bhi);
    cudaGetSymbolAddress((void**)&blo, g_Blo);

    static int attr_done = 0;
    if (!attr_done) {
        cudaFuncSetAttribute(gemm_mma<64, 256, 1, 0, 0>,
                             cudaFuncAttributeMaxDynamicSharedMemorySize, GEMM_SMEM_BYTES);
        cudaFuncSetAttribute(gemm_mma<256, 256, 2, 0, 1>,
                             cudaFuncAttributeMaxDynamicSharedMemorySize, GEMM_SMEM_BYTES);
        cudaFuncSetAttribute(gemm_mma<256, 128, 1, 0, 2>,
                             cudaFuncAttributeMaxDynamicSharedMemorySize, GEMM_SMEM_BYTES);
        cudaFuncSetAttribute(gemm_mma<128, 128, 2, 2, 3>,
                             cudaFuncAttributeMaxDynamicSharedMemorySize, GEMM_SMEM_BYTES);
        attr_done = 1;
    }

    int NB = (N + 1023) / 1024;
    int EB = (E + 1023) / 1024;
    int gx = (N + 63) / 64;

    // --- CSR build: launches 0,1,2 ---
    hist_kernel<<<EB, 256>>>(ei, E);
    scan_fused_kernel<<<NB, 1024>>>(N);
    scatter_kernel<<<EB, 256>>>(ei, E, N);

    // --- conv1 (agg1 = launch index 3 -> profiled) ---
    agg1_kernel<<<(N + 3) / 4, 128>>>(ea, We1, be1, x, agg1, N);
    wsplit_kernel<<<256, 256>>>(W11, W12, W21, W22);
    gemm_mma<64, 256, 1, 0, 0><<<dim3(gx, 2), 256, GEMM_SMEM_BYTES>>>(
        x, bhi, blo, b11, bufA, agg1, eps1, nullptr, nullptr, N, invN);
    gemm_mma<256, 256, 2, 0, 1><<<dim3(gx, 2), 256, GEMM_SMEM_BYTES>>>(
        bufA, bhi + 8192, blo + 8192, b12, bufB, nullptr, nullptr, g11, bt11, N, invN);
    bnrelu_kernel<<<(N * 64 + 255) / 256, 256>>>(
        (const float4*)bufB, (float4*)bufA, N * 64, g1, bt1, invN);

    // --- conv2 ---
    agg2_kernel<<<(N + 1) / 2, 128>>>(ea, We2, be2, bufA, agg2, N);
    gemm_mma<256, 128, 1, 0, 2><<<dim3(gx, 1), 256, GEMM_SMEM_BYTES>>>(
        bufA, bhi + 40960, blo + 40960, b21, bufB, agg2, eps2, nullptr, nullptr, N, invN);
    gemm_mma<128, 128, 2, 2, 3><<<dim3(gx, 1), 256, GEMM_SMEM_BYTES>>>(
        bufB, bhi + 57344, blo + 57344, b22, bufA, nullptr, nullptr, g21, bt21, N, invN);

    // --- head ---
    out_kernel<<<(N + 7) / 8, 256>>>(bufA, Wout, bout, (float*)d_out, N, g2, bt2, invN);
}

// round 15
// speedup vs baseline: 1.2148x; 1.0308x over previous
#include <cuda_runtime.h>
#include <stdint.h>

// ---------------------------------------------------------------------------
// GINE 2-layer GNN, N=25000, E=400000, 64 -> 256 -> 256 -> 128 -> 128 -> 1
// R15: R14 baseline (285.0us) + 4-edge-unrolled aggregation loops (broadcast
// index loads, gathers batched before compute -> 2x memory parallelism).
// ---------------------------------------------------------------------------
#define MAXN 25000
#define MAXE 400000

__device__ float g_bufA[MAXN * 256];
__device__ float g_bufB[MAXN * 256];
__device__ float g_agg1[MAXN * 64];
__device__ float g_agg2[MAXN * 256];
__device__ float g_colsum[4][256];
__device__ float g_colsq[4][256];
__device__ int   g_deg[MAXN];        // zero-init; re-zeroed by scatter each call
__device__ int   g_rowptr[MAXN + 1];
__device__ int   g_fill[MAXN];
__device__ int   g_blocksum[32];
__device__ int   g_scanflag[32];     // zero-init; re-zeroed by scatter each call
__device__ int2  g_eperm[MAXE];
// k-major bf16x2 weight tiles, [nb][kc] order, each tile 128 rows x 16 u32.
__device__ uint32_t g_Bhi[65536];
__device__ uint32_t g_Blo[65536];

__device__ __forceinline__ uint32_t packbf(float fhi, float flo) {
    uint32_t r;
    asm("cvt.rn.bf16x2.f32 %0, %1, %2;" : "=r"(r) : "f"(fhi), "f"(flo));
    return r;
}
__device__ __forceinline__ void cp16(uint32_t saddr, const void* g) {
    asm volatile("cp.async.cg.shared.global [%0], [%1], 16;" :: "r"(saddr), "l"(g));
}
__device__ __forceinline__ void cp_commit() {
    asm volatile("cp.async.commit_group;" ::: "memory");
}
__device__ __forceinline__ void cp_wait0() {
    asm volatile("cp.async.wait_group 0;" ::: "memory");
}
__device__ __forceinline__ void ldsm4(uint32_t& r0, uint32_t& r1,
                                      uint32_t& r2, uint32_t& r3, uint32_t a) {
    asm volatile("ldmatrix.sync.aligned.m8n8.x4.shared.b16 {%0,%1,%2,%3}, [%4];"
                 : "=r"(r0), "=r"(r1), "=r"(r2), "=r"(r3) : "r"(a));
}

// per-block edge_index dtype detect: sample first 256 odd 32-bit words.
__device__ __forceinline__ int detect_idx64(const int* e32) {
    int nz = (threadIdx.x < 256) ? (e32[2 * threadIdx.x + 1] != 0) : 0;
    return __syncthreads_or(nz) ? 0 : 1;
}

// ---------------------------------------------------------------------------
// hist (launch 0): zero BN stats, inline dtype detect, degree histogram.
// ---------------------------------------------------------------------------
__global__ void hist_kernel(const void* __restrict__ eiv, int E) {
    int f = detect_idx64((const int*)eiv);
    int gb = blockIdx.x * blockDim.x + threadIdx.x;
    if (gb < 1024) {
        ((float*)g_colsum)[gb] = 0.f;
        ((float*)g_colsq)[gb]  = 0.f;
    }
    int base = gb * 4;
    if (base >= E) return;
    int cnt = min(4, E - base);
    int d[4];
    bool al = ((E & 3) == 0);
    if (f) {
        const long long* p = (const long long*)eiv;
        if (cnt == 4 && al) {
            longlong2 d01 = *(const longlong2*)(p + E + base);
            longlong2 d23 = *(const longlong2*)(p + E + base + 2);
            d[0] = (int)d01.x; d[1] = (int)d01.y; d[2] = (int)d23.x; d[3] = (int)d23.y;
        } else {
            for (int j = 0; j < cnt; j++) d[j] = (int)p[E + base + j];
        }
    } else {
        const int* p = (const int*)eiv;
        if (cnt == 4 && al) {
            int4 dv = *(const int4*)(p + E + base);
            d[0] = dv.x; d[1] = dv.y; d[2] = dv.z; d[3] = dv.w;
        } else {
            for (int j = 0; j < cnt; j++) d[j] = p[E + base + j];
        }
    }
    for (int j = 0; j < cnt; j++) atomicAdd(&g_deg[d[j]], 1);
}

// ---------------------------------------------------------------------------
// scan (launch 1): fused reduce+scan, decoupled lookback (25 co-resident blocks)
// ---------------------------------------------------------------------------
__global__ void scan_fused_kernel(int N) {
    __shared__ int woff[32];
    __shared__ int boff;
    int tid = threadIdx.x, lane = tid & 31, wid = tid >> 5;
    int b = blockIdx.x;
    int i = b * 1024 + tid;
    int v = (i < N) ? g_deg[i] : 0;
    int incl = v;
#pragma unroll
    for (int o = 1; o < 32; o <<= 1) {
        int t = __shfl_up_sync(0xffffffffu, incl, o);
        if (lane >= o) incl += t;
    }
    if (lane == 31) woff[wid] = incl;
    __syncthreads();
    if (wid == 0) {
        int s = woff[lane];
        int si = s;
#pragma unroll
        for (int o = 1; o < 32; o <<= 1) {
            int t = __shfl_up_sync(0xffffffffu, si, o);
            if (lane >= o) si += t;
        }
        woff[lane] = si - s;
        int total = __shfl_sync(0xffffffffu, si, 31);
        if (lane == 0) {
            atomicExch(&g_blocksum[b], total);
            __threadfence();
            atomicExch(&g_scanflag[b], 1);
        }
        int bs = 0;
        if (lane < b) {
            while (atomicAdd(&g_scanflag[lane], 0) == 0) {}
            bs = atomicAdd(&g_blocksum[lane], 0);
        }
#pragma unroll
        for (int o = 16; o > 0; o >>= 1) bs += __shfl_xor_sync(0xffffffffu, bs, o);
        if (lane == 0) boff = bs;
    }
    __syncthreads();
    int start = boff + woff[wid] + incl - v;
    if (i < N) {
        g_rowptr[i] = start;
        g_fill[i]   = start;
    }
    if (i == N - 1) g_rowptr[N] = start + v;
}

// ---------------------------------------------------------------------------
// scatter (launch 2): CSR scatter + rezero deg/scanflag for next call.
// ---------------------------------------------------------------------------
__global__ void scatter_kernel(const void* __restrict__ eiv, int E, int N) {
    int f = detect_idx64((const int*)eiv);
    int gb = blockIdx.x * blockDim.x + threadIdx.x;
    int base = gb * 4;
    if (base < E) {
        int cnt = min(4, E - base);
        int s[4], d[4];
        bool al = ((E & 3) == 0);
        if (f) {
            const long long* p = (const long long*)eiv;
            if (cnt == 4 && al) {
                longlong2 s01 = *(const longlong2*)(p + base);
                longlong2 s23 = *(const longlong2*)(p + base + 2);
                longlong2 d01 = *(const longlong2*)(p + E + base);
                longlong2 d23 = *(const longlong2*)(p + E + base + 2);
                s[0] = (int)s01.x; s[1] = (int)s01.y; s[2] = (int)s23.x; s[3] = (int)s23.y;
                d[0] = (int)d01.x; d[1] = (int)d01.y; d[2] = (int)d23.x; d[3] = (int)d23.y;
            } else {
                for (int j = 0; j < cnt; j++) { s[j] = (int)p[base + j]; d[j] = (int)p[E + base + j]; }
            }
        } else {
            const int* p = (const int*)eiv;
            if (cnt == 4 && al) {
                int4 sv = *(const int4*)(p + base);
                int4 dv = *(const int4*)(p + E + base);
                s[0] = sv.x; s[1] = sv.y; s[2] = sv.z; s[3] = sv.w;
                d[0] = dv.x; d[1] = dv.y; d[2] = dv.z; d[3] = dv.w;
            } else {
                for (int j = 0; j < cnt; j++) { s[j] = p[base + j]; d[j] = p[E + base + j]; }
            }
        }
        for (int j = 0; j < cnt; j++) {
            int pos = atomicAdd(&g_fill[d[j]], 1);
            g_eperm[pos] = make_int2(s[j], base + j);
        }
    }
    if (gb < N) g_deg[gb] = 0;
    if (gb < 32) g_scanflag[gb] = 0;
}

// ---------------------------------------------------------------------------
// agg1 (launch 3 -> PROFILED): warp per node, d=64, 2 cols/lane, W in regs.
// Broadcast eperm loads, 4-edge unroll (gathers batched before compute).
// ---------------------------------------------------------------------------
__global__ void __launch_bounds__(128) agg1_kernel(
    const float* __restrict__ ea,
    const float* __restrict__ We, const float* __restrict__ be,
    const float* __restrict__ x, float* __restrict__ agg, int N)
{
    int tid = threadIdx.x, lane = tid & 31, wid = tid >> 5;
    int node = blockIdx.x * 4 + wid;
    if (node >= N) return;
    int c0 = lane * 2;
    float w0[8], w1[8];
#pragma unroll
    for (int k = 0; k < 8; k++) {
        float2 wv = *(const float2*)(We + k * 64 + c0);
        w0[k] = wv.x; w1[k] = wv.y;
    }
    float2 bv = *(const float2*)(be + c0);
    int beg = g_rowptr[node], end = g_rowptr[node + 1];
    float acc0 = 0.f, acc1 = 0.f;

    int i = beg;
    for (; i + 4 <= end; i += 4) {
        int2 p0 = __ldg(&g_eperm[i]);
        int2 p1 = __ldg(&g_eperm[i + 1]);
        int2 p2 = __ldg(&g_eperm[i + 2]);
        int2 p3 = __ldg(&g_eperm[i + 3]);
        int pe[4] = {p0.y, p1.y, p2.y, p3.y};
        int ps[4] = {p0.x, p1.x, p2.x, p3.x};

        float4 eA[4], eB[4];
        float2 xv[4];
#pragma unroll
        for (int t = 0; t < 4; t++) {
            const float4* ep = (const float4*)(ea + (size_t)pe[t] * 8);
            eA[t] = __ldg(ep);
            eB[t] = __ldg(ep + 1);
            xv[t] = *(const float2*)(x + (size_t)ps[t] * 64 + c0);
        }
#pragma unroll
        for (int t = 0; t < 4; t++) {
            float a[8] = {eA[t].x, eA[t].y, eA[t].z, eA[t].w,
                          eB[t].x, eB[t].y, eB[t].z, eB[t].w};
            float m0 = bv.x, m1 = bv.y;
#pragma unroll
            for (int k = 0; k < 8; k++) {
                m0 += a[k] * w0[k];
                m1 += a[k] * w1[k];
            }
            acc0 += fmaxf(xv[t].x + m0, 0.f);
            acc1 += fmaxf(xv[t].y + m1, 0.f);
        }
    }
    for (; i < end; i++) {
        int2 p0 = __ldg(&g_eperm[i]);
        const float4* ep = (const float4*)(ea + (size_t)p0.y * 8);
        float4 eA = __ldg(ep), eB = __ldg(ep + 1);
        float2 xv = *(const float2*)(x + (size_t)p0.x * 64 + c0);
        float a[8] = {eA.x, eA.y, eA.z, eA.w, eB.x, eB.y, eB.z, eB.w};
        float m0 = bv.x, m1 = bv.y;
#pragma unroll
        for (int k = 0; k < 8; k++) {
            m0 += a[k] * w0[k];
            m1 += a[k] * w1[k];
        }
        acc0 += fmaxf(xv.x + m0, 0.f);
        acc1 += fmaxf(xv.y + m1, 0.f);
    }
    *(float2*)(agg + (size_t)node * 64 + c0) = make_float2(acc0, acc1);
}

// ---------------------------------------------------------------------------
// agg2: 64 threads per node, d=256, 4 cols/lane, W in regs.
// Broadcast eperm loads, 4-edge unroll.
// ---------------------------------------------------------------------------
__global__ void __launch_bounds__(128) agg2_kernel(
    const float* __restrict__ ea,
    const float* __restrict__ We, const float* __restrict__ be,
    const float* __restrict__ h1, float* __restrict__ agg, int N)
{
    int tid = threadIdx.x;
    int node = blockIdx.x * 2 + (tid >> 6);
    if (node >= N) return;
    int c0 = (tid & 63) * 4;
    float w0[8], w1[8], w2[8], w3[8];
#pragma unroll
    for (int k = 0; k < 8; k++) {
        float4 wv = *(const float4*)(We + k * 256 + c0);
        w0[k] = wv.x; w1[k] = wv.y; w2[k] = wv.z; w3[k] = wv.w;
    }
    float4 bv = *(const float4*)(be + c0);
    int beg = g_rowptr[node], end = g_rowptr[node + 1];
    float ac0 = 0.f, ac1 = 0.f, ac2 = 0.f, ac3 = 0.f;

    int i = beg;
    for (; i + 4 <= end; i += 4) {
        int2 p0 = __ldg(&g_eperm[i]);
        int2 p1 = __ldg(&g_eperm[i + 1]);
        int2 p2 = __ldg(&g_eperm[i + 2]);
        int2 p3 = __ldg(&g_eperm[i + 3]);
        int pe[4] = {p0.y, p1.y, p2.y, p3.y};
        int ps[4] = {p0.x, p1.x, p2.x, p3.x};

        float4 eA[4], eB[4], hv[4];
#pragma unroll
        for (int t = 0; t < 4; t++) {
            const float4* ep = (const float4*)(ea + (size_t)pe[t] * 8);
            eA[t] = __ldg(ep);
            eB[t] = __ldg(ep + 1);
            hv[t] = *(const float4*)(h1 + (size_t)ps[t] * 256 + c0);
        }
#pragma unroll
        for (int t = 0; t < 4; t++) {
            float a[8] = {eA[t].x, eA[t].y, eA[t].z, eA[t].w,
                          eB[t].x, eB[t].y, eB[t].z, eB[t].w};
            float m0 = bv.x, m1 = bv.y, m2 = bv.z, m3 = bv.w;
#pragma unroll
            for (int k = 0; k < 8; k++) {
                m0 += a[k] * w0[k]; m1 += a[k] * w1[k];
                m2 += a[k] * w2[k]; m3 += a[k] * w3[k];
            }
            ac0 += fmaxf(hv[t].x + m0, 0.f);
            ac1 += fmaxf(hv[t].y + m1, 0.f);
            ac2 += fmaxf(hv[t].z + m2, 0.f);
            ac3 += fmaxf(hv[t].w + m3, 0.f);
        }
    }
    for (; i < end; i++) {
        int2 p0 = __ldg(&g_eperm[i]);
        const float4* ep = (const float4*)(ea + (size_t)p0.y * 8);
        float4 eA = __ldg(ep), eB = __ldg(ep + 1);
        float4 hv = *(const float4*)(h1 + (size_t)p0.x * 256 + c0);
        float a[8] = {eA.x, eA.y, eA.z, eA.w, eB.x, eB.y, eB.z, eB.w};
        float m0 = bv.x, m1 = bv.y, m2 = bv.z, m3 = bv.w;
#pragma unroll
        for (int k = 0; k < 8; k++) {
            m0 += a[k] * w0[k]; m1 += a[k] * w1[k];
            m2 += a[k] * w2[k]; m3 += a[k] * w3[k];
        }
        ac0 += fmaxf(hv.x + m0, 0.f);
        ac1 += fmaxf(hv.y + m1, 0.f);
        ac2 += fmaxf(hv.z + m2, 0.f);
        ac3 += fmaxf(hv.w + m3, 0.f);
    }
    *(float4*)(agg + (size_t)node * 256 + c0) = make_float4(ac0, ac1, ac2, ac3);
}

// ---------------------------------------------------------------------------
// wsplit: W[K][N] fp32 -> bf16 hi/lo bf16x2 (packed along K), k-major tiles.
// ---------------------------------------------------------------------------
__global__ void wsplit_kernel(const float* __restrict__ W11,
                              const float* __restrict__ W12,
                              const float* __restrict__ W21,
                              const float* __restrict__ W22) {
    int i = blockIdx.x * blockDim.x + threadIdx.x;   // < 65536
    const float* W; int Ncols, il, ktiles;
    if (i < 8192)        { W = W11; Ncols = 256; il = i;         ktiles = 2; }
    else if (i < 40960)  { W = W12; Ncols = 256; il = i - 8192;  ktiles = 8; }
    else if (i < 57344)  { W = W21; Ncols = 128; il = i - 40960; ktiles = 8; }
    else                 { W = W22; Ncols = 128; il = i - 57344; ktiles = 4; }
    int tile = il >> 11, t = il & 2047;
    int nb = tile / ktiles, kc = tile % ktiles;
    int nloc = t >> 4, j = t & 15;
    int n = nb * 128 + nloc;
    int k = kc * 32 + j * 2;
    float f0 = W[(size_t)k * Ncols + n];
    float f1 = W[(size_t)(k + 1) * Ncols + n];
    uint32_t hi = packbf(f1, f0);
    float l0 = f0 - __uint_as_float(hi << 16);
    float l1 = f1 - __uint_as_float(hi & 0xffff0000u);
    g_Bhi[i] = hi;
    g_Blo[i] = packbf(l1, l0);
}

// ---------------------------------------------------------------------------
// 3xBF16 GEMM (m16n8k16) with ldmatrix fragment loads. (unchanged)
// ---------------------------------------------------------------------------
#define MMA_BF16(d, a, b)                                                     \
    asm volatile(                                                             \
        "mma.sync.aligned.m16n8k16.row.col.f32.bf16.bf16.f32 "                \
        "{%0,%1,%2,%3},{%4,%5,%6,%7},{%8,%9},{%0,%1,%2,%3};"                  \
        : "+f"(d[0]), "+f"(d[1]), "+f"(d[2]), "+f"(d[3])                      \
        : "r"(a[0]), "r"(a[1]), "r"(a[2]), "r"(a[3]), "r"(b[0]), "r"(b[1]))

#define GA(s)   ((s) * 2560)
#define GB(s)   (5120 + (s) * 5120)
#define GSUM    15360
#define GSQ     15488
#define GAF     15616
#define GBF     15872
#define GEMM_SMEM_BYTES (16128 * 4)

template <int K, int NCOLS, int PRE, int LIN, int LOUT>
__global__ void __launch_bounds__(256) gemm_mma(
    const float* __restrict__ X,
    const uint32_t* __restrict__ WBhi, const uint32_t* __restrict__ WBlo,
    const float* __restrict__ bias, float* __restrict__ out,
    const float* __restrict__ X2, const float* __restrict__ eps_ptr,
    const float* __restrict__ gin, const float* __restrict__ btin,
    int N, float invN)
{
    constexpr int BM = 64, BN = 128, BK = 32;
    constexpr int KT = K / BK;
    constexpr int KTILES = K / 32;
    extern __shared__ uint32_t dsm[];
    float* ssum = (float*)(dsm + GSUM);
    float* ssq  = (float*)(dsm + GSQ);
    float* sAf  = (float*)(dsm + GAF);
    float* sBf  = (float*)(dsm + GBF);
    uint32_t sbase = (uint32_t)__cvta_generic_to_shared(dsm);

    int tid = threadIdx.x, lane = tid & 31, wid = tid >> 5;
    int wm = wid & 1, wn = wid >> 1;
    int n0  = blockIdx.x * BM;
    int nb0 = blockIdx.y * BN;

    for (int i = tid; i < BN; i += 256) { ssum[i] = 0.f; ssq[i] = 0.f; }
    if constexpr (PRE == 2) {
        for (int j = tid; j < K; j += 256) {
            float mu = g_colsum[LIN][j] * invN;
            float var = fmaxf(g_colsq[LIN][j] * invN - mu * mu, 0.f);
            float A = gin[j] * rsqrtf(var + 1e-5f);
            sAf[j] = A;
            sBf[j] = btin[j] - A * mu;
        }
    }
    __syncthreads();

    float eps = 0.f;
    if constexpr (PRE == 1) eps = 1.0f + *eps_ptr;

    float acc[2][4][4];
#pragma unroll
    for (int mt = 0; mt < 2; mt++)
#pragma unroll
        for (int nt = 0; nt < 4; nt++)
#pragma unroll
            for (int r = 0; r < 4; r++) acc[mt][nt][r] = 0.f;

    int a_row = tid >> 2;
    int a_q   = tid & 3;
    auto loadA = [&](int kt, float4* av) {
        int row = n0 + a_row;
        av[0] = make_float4(0.f, 0.f, 0.f, 0.f);
        av[1] = make_float4(0.f, 0.f, 0.f, 0.f);
        if (row < N) {
            int gk = kt * BK + a_q * 8;
#pragma unroll
            for (int q = 0; q < 2; q++) {
                int gkq = gk + q * 4;
                float4 v = *(const float4*)(X + (size_t)row * K + gkq);
                if constexpr (PRE == 1) {
                    float4 xv = *(const float4*)(X2 + (size_t)row * K + gkq);
                    v.x = eps * v.x + xv.x; v.y = eps * v.y + xv.y;
                    v.z = eps * v.z + xv.z; v.w = eps * v.w + xv.w;
                } else if constexpr (PRE == 2) {
                    v.x = fmaxf(sAf[gkq]     * v.x + sBf[gkq],     0.f);
                    v.y = fmaxf(sAf[gkq + 1] * v.y + sBf[gkq + 1], 0.f);
                    v.z = fmaxf(sAf[gkq + 2] * v.z + sBf[gkq + 2], 0.f);
                    v.w = fmaxf(sAf[gkq + 3] * v.w + sBf[gkq + 3], 0.f);
                }
                av[q] = v;
            }
        }
    };
    auto storeA = [&](int s, const float4* av) {
        uint32_t h[4], l[4];
#pragma unroll
        for (int q = 0; q < 2; q++) {
            uint32_t h0 = packbf(av[q].y, av[q].x);
            uint32_t h1 = packbf(av[q].w, av[q].z);
            h[q * 2]     = h0;
            h[q * 2 + 1] = h1;
            l[q * 2]     = packbf(av[q].y - __uint_as_float(h0 & 0xffff0000u),
                                  av[q].x - __uint_as_float(h0 << 16));
            l[q * 2 + 1] = packbf(av[q].w - __uint_as_float(h1 & 0xffff0000u),
                                  av[q].z - __uint_as_float(h1 << 16));
        }
        int idx = GA(s) + a_row * 20 + a_q * 4;
        *(uint4*)&dsm[idx]        = make_uint4(h[0], h[1], h[2], h[3]);
        *(uint4*)&dsm[idx + 1280] = make_uint4(l[0], l[1], l[2], l[3]);
    };
    auto loadB = [&](int kt, int s) {
        int tile = blockIdx.y * KTILES + kt;
        const uint32_t* srcH = WBhi + ((size_t)tile << 11);
        const uint32_t* srcL = WBlo + ((size_t)tile << 11);
        uint32_t dH = sbase + GB(s) * 4;
        uint32_t dL = dH + 2560 * 4;
#pragma unroll
        for (int r = 0; r < 2; r++) {
            int c = tid + r * 256;
            uint32_t off = (uint32_t)((c >> 2) * 20 + (c & 3) * 4) * 4;
            cp16(dH + off, srcH + c * 4);
            cp16(dL + off, srcL + c * 4);
        }
        cp_commit();
    };

    {
        float4 av[2];
        loadB(0, 0);
        loadA(0, av);
        storeA(0, av);
        cp_wait0();
        __syncthreads();
    }

    uint32_t aoff = (uint32_t)((wm * 32 + (lane & 7) + ((lane & 8) ? 8 : 0)) * 20
                               + ((lane & 16) ? 4 : 0));
    uint32_t boff = (uint32_t)((wn * 32 + (lane & 7) + ((lane & 16) ? 8 : 0)) * 20
                               + ((lane & 8) ? 4 : 0));

    for (int kt = 0; kt < KT; kt++) {
        int s = kt & 1;
        float4 nav[2];
        if (kt + 1 < KT) { loadB(kt + 1, s ^ 1); loadA(kt + 1, nav); }

#pragma unroll
        for (int ks = 0; ks < 2; ks++) {
            uint32_t ka = ks * 8;
            uint32_t aB = sbase + (GA(s) + ka) * 4;
            uint32_t bB = sbase + (GB(s) + ka) * 4;
            uint32_t ahi[2][4], alo[2][4];
#pragma unroll
            for (int mt = 0; mt < 2; mt++) {
                uint32_t ad = aB + (aoff + mt * 320) * 4;
                ldsm4(ahi[mt][0], ahi[mt][1], ahi[mt][2], ahi[mt][3], ad);
                ldsm4(alo[mt][0], alo[mt][1], alo[mt][2], alo[mt][3], ad + 1280 * 4);
            }
            uint32_t bhi[4][2], blo[4][2];
#pragma unroll
            for (int p = 0; p < 2; p++) {
                uint32_t bd = bB + (boff + p * 320) * 4;
                uint32_t r0, r1, r2, r3;
                ldsm4(r0, r1, r2, r3, bd);
                bhi[p * 2][0] = r0;     bhi[p * 2][1] = r1;
                bhi[p * 2 + 1][0] = r2; bhi[p * 2 + 1][1] = r3;
                ldsm4(r0, r1, r2, r3, bd + 2560 * 4);
                blo[p * 2][0] = r0;     blo[p * 2][1] = r1;
                blo[p * 2 + 1][0] = r2; blo[p * 2 + 1][1] = r3;
            }
#pragma unroll
            for (int mt = 0; mt < 2; mt++)
#pragma unroll
                for (int nt = 0; nt < 4; nt++) {
                    MMA_BF16(acc[mt][nt], ahi[mt], bhi[nt]);
                    MMA_BF16(acc[mt][nt], alo[mt], bhi[nt]);
                    MMA_BF16(acc[mt][nt], ahi[mt], blo[nt]);
                }
        }
        if (kt + 1 < KT) {
            cp_wait0();
            __syncthreads();
            storeA(s ^ 1, nav);
            __syncthreads();
        }
    }

#pragma unroll
    for (int nt = 0; nt < 4; nt++) {
        int cb = wn * 32 + nt * 8 + 2 * (lane & 3);
        float b0 = bias[nb0 + cb], b1 = bias[nb0 + cb + 1];
        float s0 = 0.f, s1 = 0.f, q0 = 0.f, q1 = 0.f;
#pragma unroll
        for (int mt = 0; mt < 2; mt++) {
            int row0 = n0 + wm * 32 + mt * 16 + (lane >> 2);
            float v0 = acc[mt][nt][0] + b0, v1 = acc[mt][nt][1] + b1;
            float v2 = acc[mt][nt][2] + b0, v3 = acc[mt][nt][3] + b1;
            if (row0 < N) {
                *(float2*)(out + (size_t)row0 * NCOLS + nb0 + cb) = make_float2(v0, v1);
                s0 += v0; s1 += v1; q0 += v0 * v0; q1 += v1 * v1;
            }
            if (row0 + 8 < N) {
                *(float2*)(out + (size_t)(row0 + 8) * NCOLS + nb0 + cb) = make_float2(v2, v3);
                s0 += v2; s1 += v3; q0 += v2 * v2; q1 += v3 * v3;
            }
        }
#pragma unroll
        for (int off = 4; off < 32; off <<= 1) {
            s0 += __shfl_xor_sync(0xffffffffu, s0, off);
            s1 += __shfl_xor_sync(0xffffffffu, s1, off);
            q0 += __shfl_xor_sync(0xffffffffu, q0, off);
            q1 += __shfl_xor_sync(0xffffffffu, q1, off);
        }
        if (lane < 4) {
            atomicAdd(&ssum[cb], s0); atomicAdd(&ssum[cb + 1], s1);
            atomicAdd(&ssq[cb],  q0); atomicAdd(&ssq[cb + 1],  q1);
        }
    }
    __syncthreads();
    for (int i = tid; i < BN; i += 256) {
        atomicAdd(&g_colsum[LOUT][nb0 + i], ssum[i]);
        atomicAdd(&g_colsq[LOUT][nb0 + i],  ssq[i]);
    }
}

// ---------------------------------------------------------------------------
// h = relu(bn(in)) with inline affine from layer-1 stats (256 cols)
// ---------------------------------------------------------------------------
__global__ void bnrelu_kernel(const float4* __restrict__ in,
                              float4* __restrict__ outp, int n4,
                              const float* __restrict__ g,
                              const float* __restrict__ bt, float invN)
{
    __shared__ float sA[256], sB[256];
    int tid = threadIdx.x;
    {
        float mu = g_colsum[1][tid] * invN;
        float var = fmaxf(g_colsq[1][tid] * invN - mu * mu, 0.f);
        float A = g[tid] * rsqrtf(var + 1e-5f);
        sA[tid] = A;
        sB[tid] = bt[tid] - A * mu;
    }
    __syncthreads();
    int i = blockIdx.x * 256 + tid;
    if (i >= n4) return;
    int c0 = (i & 63) * 4;
    float4 v = in[i];
    v.x = fmaxf(sA[c0]     * v.x + sB[c0],     0.f);
    v.y = fmaxf(sA[c0 + 1] * v.y + sB[c0 + 1], 0.f);
    v.z = fmaxf(sA[c0 + 2] * v.z + sB[c0 + 2], 0.f);
    v.w = fmaxf(sA[c0 + 3] * v.w + sB[c0 + 3], 0.f);
    outp[i] = v;
}

// ---------------------------------------------------------------------------
// Output head: out[n] = sum_j relu(bn3(t[n,j])) * Wout[j] + bout
// ---------------------------------------------------------------------------
__global__ void __launch_bounds__(256) out_kernel(
    const float* __restrict__ T, const float* __restrict__ Wout,
    const float* __restrict__ bout, float* __restrict__ out, int N,
    const float* __restrict__ g, const float* __restrict__ bt, float invN)
{
    __shared__ float sA[128], sB[128];
    int tid = threadIdx.x;
    if (tid < 128) {
        float mu = g_colsum[3][tid] * invN;
        float var = fmaxf(g_colsq[3][tid] * invN - mu * mu, 0.f);
        float A = g[tid] * rsqrtf(var + 1e-5f);
        sA[tid] = A;
        sB[tid] = bt[tid] - A * mu;
    }
    __syncthreads();
    int wid = tid >> 5, lane = tid & 31;
    int n = blockIdx.x * 8 + wid;
    if (n >= N) return;
    float4 t = ((const float4*)(T + (size_t)n * 128))[lane];
    float4 w = ((const float4*)Wout)[lane];
    int c = lane * 4;
    float s = fmaxf(sA[c]     * t.x + sB[c],     0.f) * w.x
            + fmaxf(sA[c + 1] * t.y + sB[c + 1], 0.f) * w.y
            + fmaxf(sA[c + 2] * t.z + sB[c + 2], 0.f) * w.z
            + fmaxf(sA[c + 3] * t.w + sB[c + 3], 0.f) * w.w;
#pragma unroll
    for (int o = 16; o > 0; o >>= 1)
        s += __shfl_xor_sync(0xffffffffu, s, o);
    if (lane == 0) out[n] = s + bout[0];
}

// ---------------------------------------------------------------------------
extern "C" void kernel_launch(void* const* d_in, const int* in_sizes, int n_in,
                              void* d_out, int out_size)
{
    const float* x    = (const float*)d_in[0];
    const void*  ei   = d_in[1];
    const float* ea   = (const float*)d_in[2];
    const float* eps1 = (const float*)d_in[3];
    const float* We1  = (const float*)d_in[4];
    const float* be1  = (const float*)d_in[5];
    const float* W11  = (const float*)d_in[6];
    const float* b11  = (const float*)d_in[7];
    const float* g11  = (const float*)d_in[8];
    const float* bt11 = (const float*)d_in[9];
    const float* W12  = (const float*)d_in[10];
    const float* b12  = (const float*)d_in[11];
    const float* g1   = (const float*)d_in[12];
    const float* bt1  = (const float*)d_in[13];
    const float* eps2 = (const float*)d_in[14];
    const float* We2  = (const float*)d_in[15];
    const float* be2  = (const float*)d_in[16];
    const float* W21  = (const float*)d_in[17];
    const float* b21  = (const float*)d_in[18];
    const float* g21  = (const float*)d_in[19];
    const float* bt21 = (const float*)d_in[20];
    const float* W22  = (const float*)d_in[21];
    const float* b22  = (const float*)d_in[22];
    const float* g2   = (const float*)d_in[23];
    const float* bt2  = (const float*)d_in[24];
    const float* Wout = (const float*)d_in[25];
    const float* bout = (const float*)d_in[26];

    int N = in_sizes[0] / 64;   // 25000
    int E = in_sizes[2] / 8;    // 400000
    float invN = 1.0f / (float)N;

    float *agg1, *agg2, *bufA, *bufB;
    uint32_t *bhi, *blo;
    cudaGetSymbolAddress((void**)&agg1, g_agg1);
    cudaGetSymbolAddress((void**)&agg2, g_agg2);
    cudaGetSymbolAddress((void**)&bufA, g_bufA);
    cudaGetSymbolAddress((void**)&bufB, g_bufB);
    cudaGetSymbolAddress((void**)&bhi, g_Bhi);
    cudaGetSymbolAddress((void**)&blo, g_Blo);

    static int attr_done = 0;
    if (!attr_done) {
        cudaFuncSetAttribute(gemm_mma<64, 256, 1, 0, 0>,
                             cudaFuncAttributeMaxDynamicSharedMemorySize, GEMM_SMEM_BYTES);
        cudaFuncSetAttribute(gemm_mma<256, 256, 2, 0, 1>,
                             cudaFuncAttributeMaxDynamicSharedMemorySize, GEMM_SMEM_BYTES);
        cudaFuncSetAttribute(gemm_mma<256, 128, 1, 0, 2>,
                             cudaFuncAttributeMaxDynamicSharedMemorySize, GEMM_SMEM_BYTES);
        cudaFuncSetAttribute(gemm_mma<128, 128, 2, 2, 3>,
                             cudaFuncAttributeMaxDynamicSharedMemorySize, GEMM_SMEM_BYTES);
        attr_done = 1;
    }

    int NB = (N + 1023) / 1024;
    int EB = (E + 1023) / 1024;
    int gx = (N + 63) / 64;

    // --- CSR build: launches 0,1,2 ---
    hist_kernel<<<EB, 256>>>(ei, E);
    scan_fused_kernel<<<NB, 1024>>>(N);
    scatter_kernel<<<EB, 256>>>(ei, E, N);

    // --- conv1 (agg1 = launch index 3 -> profiled) ---
    agg1_kernel<<<(N + 3) / 4, 128>>>(ea, We1, be1, x, agg1, N);
    wsplit_kernel<<<256, 256>>>(W11, W12, W21, W22);
    gemm_mma<64, 256, 1, 0, 0><<<dim3(gx, 2), 256, GEMM_SMEM_BYTES>>>(
        x, bhi, blo, b11, bufA, agg1, eps1, nullptr, nullptr, N, invN);
    gemm_mma<256, 256, 2, 0, 1><<<dim3(gx, 2), 256, GEMM_SMEM_BYTES>>>(
        bufA, bhi + 8192, blo + 8192, b12, bufB, nullptr, nullptr, g11, bt11, N, invN);
    bnrelu_kernel<<<(N * 64 + 255) / 256, 256>>>(
        (const float4*)bufB, (float4*)bufA, N * 64, g1, bt1, invN);

    // --- conv2 ---
    agg2_kernel<<<(N + 1) / 2, 128>>>(ea, We2, be2, bufA, agg2, N);
    gemm_mma<256, 128, 1, 0, 2><<<dim3(gx, 1), 256, GEMM_SMEM_BYTES>>>(
        bufA, bhi + 40960, blo + 40960, b21, bufB, agg2, eps2, nullptr, nullptr, N, invN);
    gemm_mma<128, 128, 2, 2, 3><<<dim3(gx, 1), 256, GEMM_SMEM_BYTES>>>(
        bufB, bhi + 57344, blo + 57344, b22, bufA, nullptr, nullptr, g21, bt21, N, invN);

    // --- head ---
    out_kernel<<<(N + 7) / 8, 256>>>(bufA, Wout, bout, (float*)d_out, N, g2, bt2, invN);
}